// round 1
// baseline (speedup 1.0000x reference)
#include <cuda_runtime.h>

// Problem constants
#define NUM_B 16384
#define DIM_D 784
#define DIM_L 1024
#define LAMBDA 0.3f
#define STEPSZ 0.1f

// Scratch (allocation-free rule: __device__ globals)
__device__ float g_G[DIM_L * DIM_L];                 // 4 MB   g = W^T W - I
__device__ float g_B[(size_t)NUM_B * DIM_L];         // 64 MB  b = X W
__device__ float g_U0[(size_t)NUM_B * DIM_L];        // 64 MB  u ping
__device__ float g_U1[(size_t)NUM_B * DIM_L];        // 64 MB  u pong

__device__ __forceinline__ float lca_thresh(float x) {
    return x > LAMBDA ? x - LAMBDA : 0.0f;
}

// Generic tiled fp32 GEMM. C[M,N] = op(A)[M,K] * op(B)[K,N] (+ epilogue)
// OPA: 0 = A row-major [M,K] (lda=K stride)
//      1 = thresh(A) row-major
//      2 = A[m,k] = Asrc[k*lda + m]   (A = W^T, contiguous in m)
// OPB: 0 = B row-major [K,N] (ldb)
//      1 = B[k,n] = Bsrc[n*ldb + k]   (B = W^T, contiguous in k)
// EPI: 0 = C = acc
//      1 = C = acc - I        (for g)
//      2 = C = 0.9*Uold + 0.1*Bex - 0.1*acc   (LCA update)
// NB : true => guard N bounds (recon, N=784)
template<int OPA, int OPB, int EPI, bool NB>
__global__ __launch_bounds__(256, 2)
void gemm_k(const float* __restrict__ A, const float* __restrict__ Bm,
            float* __restrict__ C,
            const float* __restrict__ Uold, const float* __restrict__ Bex,
            int M, int N, int K, int lda, int ldb)
{
    __shared__ float As[16][128];
    __shared__ float Bs[16][128];

    const int tid = threadIdx.x;
    const int m0 = blockIdx.y * 128;
    const int n0 = blockIdx.x * 128;
    const int tx = tid & 15;
    const int ty = tid >> 4;
    const int tx4 = tx * 4;
    const int ty4 = ty * 4;

    float acc[8][8];
    #pragma unroll
    for (int i = 0; i < 8; i++)
        #pragma unroll
        for (int j = 0; j < 8; j++) acc[i][j] = 0.0f;

    for (int k0 = 0; k0 < K; k0 += 16) {
        // ---------------- load A tile into As[k][m] ----------------
        if (OPA == 0 || OPA == 1) {
            const int m  = tid & 127;
            const int kq = (tid >> 7) * 8;
            const float* src = A + (size_t)(m0 + m) * lda + k0 + kq;
            float4 v0 = *(const float4*)(src);
            float4 v1 = *(const float4*)(src + 4);
            if (OPA == 1) {
                v0.x = lca_thresh(v0.x); v0.y = lca_thresh(v0.y);
                v0.z = lca_thresh(v0.z); v0.w = lca_thresh(v0.w);
                v1.x = lca_thresh(v1.x); v1.y = lca_thresh(v1.y);
                v1.z = lca_thresh(v1.z); v1.w = lca_thresh(v1.w);
            }
            As[kq + 0][m] = v0.x; As[kq + 1][m] = v0.y;
            As[kq + 2][m] = v0.z; As[kq + 3][m] = v0.w;
            As[kq + 4][m] = v1.x; As[kq + 5][m] = v1.y;
            As[kq + 6][m] = v1.z; As[kq + 7][m] = v1.w;
        } else { // OPA == 2 : A[m,k] = Asrc[k*lda + m]
            const int k  = tid >> 4;
            const int mq = (tid & 15) * 8;
            const float* src = A + (size_t)(k0 + k) * lda + m0 + mq;
            float4 v0 = *(const float4*)(src);
            float4 v1 = *(const float4*)(src + 4);
            *(float4*)&As[k][mq]     = v0;
            *(float4*)&As[k][mq + 4] = v1;
        }

        // ---------------- load B tile into Bs[k][n] ----------------
        if (OPB == 0) {
            const int k  = tid >> 4;
            const int nq = (tid & 15) * 8;
            const float* src = Bm + (size_t)(k0 + k) * ldb + n0 + nq;
            *(float4*)&Bs[k][nq]     = *(const float4*)(src);
            *(float4*)&Bs[k][nq + 4] = *(const float4*)(src + 4);
        } else { // OPB == 1 : B[k,n] = Bsrc[n*ldb + k]
            const int n  = tid & 127;
            const int kq = (tid >> 7) * 8;
            float4 v0 = make_float4(0.f, 0.f, 0.f, 0.f);
            float4 v1 = v0;
            if (!NB || (n0 + n) < N) {
                const float* src = Bm + (size_t)(n0 + n) * ldb + k0 + kq;
                v0 = *(const float4*)(src);
                v1 = *(const float4*)(src + 4);
            }
            Bs[kq + 0][n] = v0.x; Bs[kq + 1][n] = v0.y;
            Bs[kq + 2][n] = v0.z; Bs[kq + 3][n] = v0.w;
            Bs[kq + 4][n] = v1.x; Bs[kq + 5][n] = v1.y;
            Bs[kq + 6][n] = v1.z; Bs[kq + 7][n] = v1.w;
        }

        __syncthreads();

        // ---------------- FMA on the tile ----------------
        #pragma unroll
        for (int kk = 0; kk < 16; kk++) {
            float4 a0 = *(const float4*)&As[kk][ty4];
            float4 a1 = *(const float4*)&As[kk][ty4 + 64];
            float4 b0 = *(const float4*)&Bs[kk][tx4];
            float4 b1 = *(const float4*)&Bs[kk][tx4 + 64];
            float ar[8] = {a0.x, a0.y, a0.z, a0.w, a1.x, a1.y, a1.z, a1.w};
            float br[8] = {b0.x, b0.y, b0.z, b0.w, b1.x, b1.y, b1.z, b1.w};
            #pragma unroll
            for (int i = 0; i < 8; i++)
                #pragma unroll
                for (int j = 0; j < 8; j++)
                    acc[i][j] += ar[i] * br[j];
        }

        __syncthreads();
    }

    // ---------------- epilogue ----------------
    #pragma unroll
    for (int ih = 0; ih < 2; ih++) {
        #pragma unroll
        for (int ii = 0; ii < 4; ii++) {
            const int row = m0 + ih * 64 + ty4 + ii;
            #pragma unroll
            for (int jh = 0; jh < 2; jh++) {
                const int col = n0 + jh * 64 + tx4;
                if (NB && col >= N) continue;
                const size_t idx = (size_t)row * N + col;
                float4 v;
                v.x = acc[ih * 4 + ii][jh * 4 + 0];
                v.y = acc[ih * 4 + ii][jh * 4 + 1];
                v.z = acc[ih * 4 + ii][jh * 4 + 2];
                v.w = acc[ih * 4 + ii][jh * 4 + 3];
                if (EPI == 1) {
                    if (row == col + 0) v.x -= 1.0f;
                    if (row == col + 1) v.y -= 1.0f;
                    if (row == col + 2) v.z -= 1.0f;
                    if (row == col + 3) v.w -= 1.0f;
                } else if (EPI == 2) {
                    const float4 uo = *(const float4*)&Uold[idx];
                    const float4 be = *(const float4*)&Bex[idx];
                    v.x = (1.0f - STEPSZ) * uo.x + STEPSZ * be.x - STEPSZ * v.x;
                    v.y = (1.0f - STEPSZ) * uo.y + STEPSZ * be.y - STEPSZ * v.y;
                    v.z = (1.0f - STEPSZ) * uo.z + STEPSZ * be.z - STEPSZ * v.z;
                    v.w = (1.0f - STEPSZ) * uo.w + STEPSZ * be.w - STEPSZ * v.w;
                }
                *(float4*)&C[idx] = v;
            }
        }
    }
}

// u after step 1 (u0 = 0): u = STEP * b
__global__ void init_u_kernel(const float* __restrict__ b, float* __restrict__ u) {
    const size_t i = (size_t)blockIdx.x * blockDim.x + threadIdx.x;
    float4 v = ((const float4*)b)[i];
    v.x *= STEPSZ; v.y *= STEPSZ; v.z *= STEPSZ; v.w *= STEPSZ;
    ((float4*)u)[i] = v;
}

extern "C" void kernel_launch(void* const* d_in, const int* in_sizes, int n_in,
                              void* d_out, int out_size) {
    (void)n_in; (void)out_size;

    const float* x = (const float*)d_in[0];
    const float* w = (const float*)d_in[1];
    // Defensive: sizes are distinct, so detect ordering.
    if (in_sizes[0] == DIM_D * DIM_L) {
        x = (const float*)d_in[1];
        w = (const float*)d_in[0];
    }
    float* out = (float*)d_out;

    float *G, *Bb, *U0, *U1;
    cudaGetSymbolAddress((void**)&G,  g_G);
    cudaGetSymbolAddress((void**)&Bb, g_B);
    cudaGetSymbolAddress((void**)&U0, g_U0);
    cudaGetSymbolAddress((void**)&U1, g_U1);

    const dim3 blk(256);

    // g = W^T W - I   (M=N=1024, K=784)
    gemm_k<2, 0, 1, false><<<dim3(8, 8), blk>>>(
        w, w, G, nullptr, nullptr, DIM_L, DIM_L, DIM_D, DIM_L, DIM_L);

    // b = X W         (M=16384, N=1024, K=784)
    gemm_k<0, 0, 0, false><<<dim3(8, 128), blk>>>(
        x, w, Bb, nullptr, nullptr, NUM_B, DIM_L, DIM_D, DIM_D, DIM_L);

    // step 1: u = 0.1 * b
    init_u_kernel<<<(NUM_B * DIM_L) / 4 / 256, 256>>>(Bb, U0);

    // steps 2..49: u_out = 0.9*u_in + 0.1*b - 0.1*(thresh(u_in) @ g)
    float* uin = U0;
    float* uout = U1;
    for (int s = 0; s < 48; s++) {
        gemm_k<1, 0, 2, false><<<dim3(8, 128), blk>>>(
            uin, G, uout, uin, Bb, NUM_B, DIM_L, DIM_L, DIM_L, DIM_L);
        float* t = uin; uin = uout; uout = t;
    }
    // 48 swaps from U0 -> final u is back in U0 (== uin)

    // recon = thresh(u) @ W^T   (M=16384, N=784, K=1024)
    gemm_k<1, 1, 0, true><<<dim3(7, 128), blk>>>(
        uin, w, out, nullptr, nullptr, NUM_B, DIM_D, DIM_L, DIM_L, DIM_L);
}

// round 3
// speedup vs baseline: 2.0924x; 2.0924x over previous
#include <cuda_runtime.h>
#include <cuda_bf16.h>
#include <cstdint>

// Problem constants
#define NUM_B 16384
#define DIM_D 784
#define DIM_L 1024
#define LAMBDA 0.3f
#define STEPSZ 0.1f

// ---------------- scratch (__device__ globals; no allocs allowed) ----------
__device__ float g_G [DIM_L * DIM_L];
__device__ float g_B [(size_t)NUM_B * DIM_L];
__device__ float g_U0[(size_t)NUM_B * DIM_L];
__device__ float g_U1[(size_t)NUM_B * DIM_L];
__device__ __nv_bfloat16 g_A0h[(size_t)NUM_B * DIM_L];
__device__ __nv_bfloat16 g_A0l[(size_t)NUM_B * DIM_L];
__device__ __nv_bfloat16 g_A1h[(size_t)NUM_B * DIM_L];
__device__ __nv_bfloat16 g_A1l[(size_t)NUM_B * DIM_L];
__device__ __nv_bfloat16 g_Gh[DIM_L * DIM_L];
__device__ __nv_bfloat16 g_Gl[DIM_L * DIM_L];

__device__ __forceinline__ float lca_thresh(float x) {
    return x > LAMBDA ? x - LAMBDA : 0.0f;
}

// ---------------- baseline-ISA tensor helpers (sm_80+, valid on sm_103) ----
__device__ __forceinline__ uint32_t smem_u32(const void* p) {
    uint32_t a;
    asm("{ .reg .u64 t; cvta.to.shared.u64 t, %1; cvt.u32.u64 %0, t; }"
        : "=r"(a) : "l"(p));
    return a;
}
__device__ __forceinline__ void cp16(uint32_t dst, const void* src) {
    asm volatile("cp.async.cg.shared.global [%0], [%1], 16;"
                 :: "r"(dst), "l"(src) : "memory");
}
__device__ __forceinline__ void cp_commit_wait() {
    asm volatile("cp.async.commit_group;" ::: "memory");
    asm volatile("cp.async.wait_group 0;" ::: "memory");
}
__device__ __forceinline__ void ldsm_x4(uint32_t* r, uint32_t a) {
    asm volatile("ldmatrix.sync.aligned.m8n8.x4.shared.b16 {%0,%1,%2,%3}, [%4];"
                 : "=r"(r[0]), "=r"(r[1]), "=r"(r[2]), "=r"(r[3]) : "r"(a));
}
__device__ __forceinline__ void ldsm_x2(uint32_t* r, uint32_t a) {
    asm volatile("ldmatrix.sync.aligned.m8n8.x2.shared.b16 {%0,%1}, [%2];"
                 : "=r"(r[0]), "=r"(r[1]) : "r"(a));
}
__device__ __forceinline__ void mma_bf16(float* c, const uint32_t* a, const uint32_t* b) {
    asm volatile(
        "mma.sync.aligned.m16n8k16.row.col.f32.bf16.bf16.f32 "
        "{%0,%1,%2,%3}, {%4,%5,%6,%7}, {%8,%9}, {%0,%1,%2,%3};"
        : "+f"(c[0]), "+f"(c[1]), "+f"(c[2]), "+f"(c[3])
        : "r"(a[0]), "r"(a[1]), "r"(a[2]), "r"(a[3]), "r"(b[0]), "r"(b[1]));
}

// ============================================================================
// LCA step via mma.sync bf16x3:  D = a@G,  u' = 0.9u + 0.1b - 0.1D,
// fused write of u' (fp32) and thresh(u') hi/lo (bf16) for next step.
// Grid (8,128), 256 threads (8 warps, 2x4 warp grid, 64x32 per warp).
// ============================================================================
#define BK  32
#define PAD 40   // bf16 elems per SMEM row (80B: 16B-aligned, ldmatrix conflict-free)

__global__ __launch_bounds__(256, 2)
void lca_step_mma(const __nv_bfloat16* __restrict__ Ahi,
                  const __nv_bfloat16* __restrict__ Alo,
                  const __nv_bfloat16* __restrict__ Ghi,
                  const __nv_bfloat16* __restrict__ Glo,
                  const float* __restrict__ Uin,
                  const float* __restrict__ Bex,
                  float* __restrict__ Uout,
                  __nv_bfloat16* __restrict__ AhiOut,
                  __nv_bfloat16* __restrict__ AloOut)
{
    __shared__ __align__(16) __nv_bfloat16 sAh[128 * PAD];
    __shared__ __align__(16) __nv_bfloat16 sAl[128 * PAD];
    __shared__ __align__(16) __nv_bfloat16 sGh[128 * PAD];
    __shared__ __align__(16) __nv_bfloat16 sGl[128 * PAD];

    const int tid  = threadIdx.x;
    const int lane = tid & 31;
    const int wid  = tid >> 5;
    const int wy   = wid >> 2;   // 0..1  (M)
    const int wx   = wid & 3;    // 0..3  (N)
    const int m0   = blockIdx.y * 128;
    const int n0   = blockIdx.x * 128;

    const uint32_t uAh = smem_u32(sAh);
    const uint32_t uAl = smem_u32(sAl);
    const uint32_t uGh = smem_u32(sGh);
    const uint32_t uGl = smem_u32(sGl);

    // ldmatrix lane addressing (byte offsets within a tile)
    // A (x4): lanes 0-15 -> rows 0-15 @ khalf 0 ; lanes 16-31 -> rows 0-15 @ khalf 1
    const int a_row = lane & 15;
    const int a_kh  = lane >> 4;           // 0/1
    // B (x2): lanes 0-7 -> rows(n) 0-7 @ khalf 0 ; 8-15 -> @ khalf 1
    const int b_row = lane & 7;
    const int b_kh  = (lane >> 3) & 1;

    float acc[4][4][4];
    #pragma unroll
    for (int i = 0; i < 4; i++)
        #pragma unroll
        for (int j = 0; j < 4; j++)
            #pragma unroll
            for (int q = 0; q < 4; q++) acc[i][j][q] = 0.0f;

    // global load mapping: 2 x 16B per thread per tile
    const int v0row = tid >> 2;           // 0..63
    const int v0kq  = (tid & 3) * 8;
    const int v1row = (tid + 256) >> 2;   // 64..127
    const int v1kq  = v0kq;

    #pragma unroll 1
    for (int kc = 0; kc < DIM_L / BK; kc++) {
        const int k0 = kc * BK;
        {
            const uint32_t s0 = (uint32_t)(v0row * PAD + v0kq) * 2;
            const uint32_t s1 = (uint32_t)(v1row * PAD + v1kq) * 2;
            const size_t ga0 = (size_t)(m0 + v0row) * DIM_L + k0 + v0kq;
            const size_t ga1 = (size_t)(m0 + v1row) * DIM_L + k0 + v1kq;
            const size_t gg0 = (size_t)(n0 + v0row) * DIM_L + k0 + v0kq;
            const size_t gg1 = (size_t)(n0 + v1row) * DIM_L + k0 + v1kq;
            cp16(uAh + s0, Ahi + ga0);  cp16(uAh + s1, Ahi + ga1);
            cp16(uAl + s0, Alo + ga0);  cp16(uAl + s1, Alo + ga1);
            cp16(uGh + s0, Ghi + gg0);  cp16(uGh + s1, Ghi + gg1);
            cp16(uGl + s0, Glo + gg0);  cp16(uGl + s1, Glo + gg1);
        }
        cp_commit_wait();
        __syncthreads();

        #pragma unroll
        for (int kk = 0; kk < BK; kk += 16) {
            uint32_t af[4][4];
            uint32_t bf[4][2];

            // --- B = G_hi frags ---
            #pragma unroll
            for (int ni = 0; ni < 4; ni++) {
                const uint32_t boff =
                    (uint32_t)((wx * 32 + ni * 8 + b_row) * PAD + b_kh * 8 + kk) * 2;
                ldsm_x2(bf[ni], uGh + boff);
            }
            // --- A = a_hi ---
            #pragma unroll
            for (int mi = 0; mi < 4; mi++) {
                const uint32_t aoff =
                    (uint32_t)((wy * 64 + mi * 16 + a_row) * PAD + a_kh * 8 + kk) * 2;
                ldsm_x4(af[mi], uAh + aoff);
            }
            #pragma unroll
            for (int mi = 0; mi < 4; mi++)
                #pragma unroll
                for (int ni = 0; ni < 4; ni++)
                    mma_bf16(acc[mi][ni], af[mi], bf[ni]);

            // --- A = a_lo  (B still G_hi) ---
            #pragma unroll
            for (int mi = 0; mi < 4; mi++) {
                const uint32_t aoff =
                    (uint32_t)((wy * 64 + mi * 16 + a_row) * PAD + a_kh * 8 + kk) * 2;
                ldsm_x4(af[mi], uAl + aoff);
            }
            #pragma unroll
            for (int mi = 0; mi < 4; mi++)
                #pragma unroll
                for (int ni = 0; ni < 4; ni++)
                    mma_bf16(acc[mi][ni], af[mi], bf[ni]);

            // --- B = G_lo, A = a_hi ---
            #pragma unroll
            for (int ni = 0; ni < 4; ni++) {
                const uint32_t boff =
                    (uint32_t)((wx * 32 + ni * 8 + b_row) * PAD + b_kh * 8 + kk) * 2;
                ldsm_x2(bf[ni], uGl + boff);
            }
            #pragma unroll
            for (int mi = 0; mi < 4; mi++) {
                const uint32_t aoff =
                    (uint32_t)((wy * 64 + mi * 16 + a_row) * PAD + a_kh * 8 + kk) * 2;
                ldsm_x4(af[mi], uAh + aoff);
            }
            #pragma unroll
            for (int mi = 0; mi < 4; mi++)
                #pragma unroll
                for (int ni = 0; ni < 4; ni++)
                    mma_bf16(acc[mi][ni], af[mi], bf[ni]);
        }
        __syncthreads();
    }

    // ---------------- fused epilogue ----------------
    const int g  = lane >> 2;
    const int tg = lane & 3;
    #pragma unroll
    for (int mi = 0; mi < 4; mi++) {
        #pragma unroll
        for (int ni = 0; ni < 4; ni++) {
            const int r0 = m0 + wy * 64 + mi * 16 + g;
            const int c0 = n0 + wx * 32 + ni * 8 + tg * 2;
            #pragma unroll
            for (int h = 0; h < 2; h++) {
                const size_t idx = (size_t)(r0 + h * 8) * DIM_L + c0;
                const float d0 = acc[mi][ni][h * 2 + 0];
                const float d1 = acc[mi][ni][h * 2 + 1];
                const float2 u2 = *(const float2*)(Uin + idx);
                const float2 b2 = *(const float2*)(Bex + idx);
                float vx = (1.0f - STEPSZ) * u2.x + STEPSZ * b2.x - STEPSZ * d0;
                float vy = (1.0f - STEPSZ) * u2.y + STEPSZ * b2.y - STEPSZ * d1;
                *(float2*)(Uout + idx) = make_float2(vx, vy);
                const float a0 = lca_thresh(vx), a1 = lca_thresh(vy);
                const __nv_bfloat16 h0 = __float2bfloat16(a0);
                const __nv_bfloat16 h1 = __float2bfloat16(a1);
                const __nv_bfloat16 l0 = __float2bfloat16(a0 - __bfloat162float(h0));
                const __nv_bfloat16 l1 = __float2bfloat16(a1 - __bfloat162float(h1));
                *(uint32_t*)(AhiOut + idx) =
                    ((uint32_t)__bfloat16_as_ushort(h1) << 16) | __bfloat16_as_ushort(h0);
                *(uint32_t*)(AloOut + idx) =
                    ((uint32_t)__bfloat16_as_ushort(l1) << 16) | __bfloat16_as_ushort(l0);
            }
        }
    }
}

// ============================================================================
// SIMT fp32 GEMM (R1) for g, b, recon
// ============================================================================
template<int OPA, int OPB, int EPI, bool NB>
__global__ __launch_bounds__(256, 2)
void gemm_k(const float* __restrict__ A, const float* __restrict__ Bm,
            float* __restrict__ C,
            int M, int N, int K, int lda, int ldb)
{
    __shared__ float As[16][128];
    __shared__ float Bs[16][128];

    const int tid = threadIdx.x;
    const int m0 = blockIdx.y * 128;
    const int n0 = blockIdx.x * 128;
    const int tx4 = (tid & 15) * 4;
    const int ty4 = (tid >> 4) * 4;

    float acc[8][8];
    #pragma unroll
    for (int i = 0; i < 8; i++)
        #pragma unroll
        for (int j = 0; j < 8; j++) acc[i][j] = 0.0f;

    for (int k0 = 0; k0 < K; k0 += 16) {
        if (OPA == 0 || OPA == 1) {
            const int m  = tid & 127;
            const int kq = (tid >> 7) * 8;
            const float* src = A + (size_t)(m0 + m) * lda + k0 + kq;
            float4 v0 = *(const float4*)(src);
            float4 v1 = *(const float4*)(src + 4);
            if (OPA == 1) {
                v0.x = lca_thresh(v0.x); v0.y = lca_thresh(v0.y);
                v0.z = lca_thresh(v0.z); v0.w = lca_thresh(v0.w);
                v1.x = lca_thresh(v1.x); v1.y = lca_thresh(v1.y);
                v1.z = lca_thresh(v1.z); v1.w = lca_thresh(v1.w);
            }
            As[kq + 0][m] = v0.x; As[kq + 1][m] = v0.y;
            As[kq + 2][m] = v0.z; As[kq + 3][m] = v0.w;
            As[kq + 4][m] = v1.x; As[kq + 5][m] = v1.y;
            As[kq + 6][m] = v1.z; As[kq + 7][m] = v1.w;
        } else {
            const int k  = tid >> 4;
            const int mq = (tid & 15) * 8;
            const float* src = A + (size_t)(k0 + k) * lda + m0 + mq;
            *(float4*)&As[k][mq]     = *(const float4*)(src);
            *(float4*)&As[k][mq + 4] = *(const float4*)(src + 4);
        }

        if (OPB == 0) {
            const int k  = tid >> 4;
            const int nq = (tid & 15) * 8;
            const float* src = Bm + (size_t)(k0 + k) * ldb + n0 + nq;
            *(float4*)&Bs[k][nq]     = *(const float4*)(src);
            *(float4*)&Bs[k][nq + 4] = *(const float4*)(src + 4);
        } else {
            const int n  = tid & 127;
            const int kq = (tid >> 7) * 8;
            float4 v0 = make_float4(0.f, 0.f, 0.f, 0.f);
            float4 v1 = v0;
            if (!NB || (n0 + n) < N) {
                const float* src = Bm + (size_t)(n0 + n) * ldb + k0 + kq;
                v0 = *(const float4*)(src);
                v1 = *(const float4*)(src + 4);
            }
            Bs[kq + 0][n] = v0.x; Bs[kq + 1][n] = v0.y;
            Bs[kq + 2][n] = v0.z; Bs[kq + 3][n] = v0.w;
            Bs[kq + 4][n] = v1.x; Bs[kq + 5][n] = v1.y;
            Bs[kq + 6][n] = v1.z; Bs[kq + 7][n] = v1.w;
        }

        __syncthreads();

        #pragma unroll
        for (int kk = 0; kk < 16; kk++) {
            float4 a0 = *(const float4*)&As[kk][ty4];
            float4 a1 = *(const float4*)&As[kk][ty4 + 64];
            float4 b0 = *(const float4*)&Bs[kk][tx4];
            float4 b1 = *(const float4*)&Bs[kk][tx4 + 64];
            float ar[8] = {a0.x, a0.y, a0.z, a0.w, a1.x, a1.y, a1.z, a1.w};
            float br[8] = {b0.x, b0.y, b0.z, b0.w, b1.x, b1.y, b1.z, b1.w};
            #pragma unroll
            for (int i = 0; i < 8; i++)
                #pragma unroll
                for (int j = 0; j < 8; j++)
                    acc[i][j] += ar[i] * br[j];
        }

        __syncthreads();
    }

    #pragma unroll
    for (int ih = 0; ih < 2; ih++) {
        #pragma unroll
        for (int ii = 0; ii < 4; ii++) {
            const int row = m0 + ih * 64 + ty4 + ii;
            #pragma unroll
            for (int jh = 0; jh < 2; jh++) {
                const int col = n0 + jh * 64 + tx4;
                if (NB && col >= N) continue;
                const size_t idx = (size_t)row * N + col;
                float4 v;
                v.x = acc[ih * 4 + ii][jh * 4 + 0];
                v.y = acc[ih * 4 + ii][jh * 4 + 1];
                v.z = acc[ih * 4 + ii][jh * 4 + 2];
                v.w = acc[ih * 4 + ii][jh * 4 + 3];
                if (EPI == 1) {
                    if (row == col + 0) v.x -= 1.0f;
                    if (row == col + 1) v.y -= 1.0f;
                    if (row == col + 2) v.z -= 1.0f;
                    if (row == col + 3) v.w -= 1.0f;
                }
                *(float4*)&C[idx] = v;
            }
        }
    }
}

// split fp32 -> bf16 hi/lo
__global__ void split_kernel(const float* __restrict__ src,
                             __nv_bfloat16* __restrict__ hi,
                             __nv_bfloat16* __restrict__ lo)
{
    const size_t i = ((size_t)blockIdx.x * blockDim.x + threadIdx.x) * 4;
    const float4 v = *(const float4*)(src + i);
    uint32_t hp[2], lp[2];
    const __nv_bfloat16 h0 = __float2bfloat16(v.x), h1 = __float2bfloat16(v.y);
    const __nv_bfloat16 h2 = __float2bfloat16(v.z), h3 = __float2bfloat16(v.w);
    const __nv_bfloat16 l0 = __float2bfloat16(v.x - __bfloat162float(h0));
    const __nv_bfloat16 l1 = __float2bfloat16(v.y - __bfloat162float(h1));
    const __nv_bfloat16 l2 = __float2bfloat16(v.z - __bfloat162float(h2));
    const __nv_bfloat16 l3 = __float2bfloat16(v.w - __bfloat162float(h3));
    hp[0] = ((uint32_t)__bfloat16_as_ushort(h1) << 16) | __bfloat16_as_ushort(h0);
    hp[1] = ((uint32_t)__bfloat16_as_ushort(h3) << 16) | __bfloat16_as_ushort(h2);
    lp[0] = ((uint32_t)__bfloat16_as_ushort(l1) << 16) | __bfloat16_as_ushort(l0);
    lp[1] = ((uint32_t)__bfloat16_as_ushort(l3) << 16) | __bfloat16_as_ushort(l2);
    *(uint2*)(hi + i) = *(const uint2*)hp;
    *(uint2*)(lo + i) = *(const uint2*)lp;
}

// u1 = 0.1*b; a1 = thresh(u1) split hi/lo
__global__ void init_u_kernel(const float* __restrict__ b, float* __restrict__ u,
                              __nv_bfloat16* __restrict__ hi,
                              __nv_bfloat16* __restrict__ lo)
{
    const size_t i = ((size_t)blockIdx.x * blockDim.x + threadIdx.x) * 4;
    float4 v = *(const float4*)(b + i);
    v.x *= STEPSZ; v.y *= STEPSZ; v.z *= STEPSZ; v.w *= STEPSZ;
    *(float4*)(u + i) = v;
    const float a0 = lca_thresh(v.x), a1 = lca_thresh(v.y);
    const float a2 = lca_thresh(v.z), a3 = lca_thresh(v.w);
    uint32_t hp[2], lp[2];
    const __nv_bfloat16 h0 = __float2bfloat16(a0), h1 = __float2bfloat16(a1);
    const __nv_bfloat16 h2 = __float2bfloat16(a2), h3 = __float2bfloat16(a3);
    const __nv_bfloat16 l0 = __float2bfloat16(a0 - __bfloat162float(h0));
    const __nv_bfloat16 l1 = __float2bfloat16(a1 - __bfloat162float(h1));
    const __nv_bfloat16 l2 = __float2bfloat16(a2 - __bfloat162float(h2));
    const __nv_bfloat16 l3 = __float2bfloat16(a3 - __bfloat162float(h3));
    hp[0] = ((uint32_t)__bfloat16_as_ushort(h1) << 16) | __bfloat16_as_ushort(h0);
    hp[1] = ((uint32_t)__bfloat16_as_ushort(h3) << 16) | __bfloat16_as_ushort(h2);
    lp[0] = ((uint32_t)__bfloat16_as_ushort(l1) << 16) | __bfloat16_as_ushort(l0);
    lp[1] = ((uint32_t)__bfloat16_as_ushort(l3) << 16) | __bfloat16_as_ushort(l2);
    *(uint2*)(hi + i) = *(const uint2*)hp;
    *(uint2*)(lo + i) = *(const uint2*)lp;
}

// ============================================================================
extern "C" void kernel_launch(void* const* d_in, const int* in_sizes, int n_in,
                              void* d_out, int out_size) {
    (void)n_in; (void)out_size;

    const float* x = (const float*)d_in[0];
    const float* w = (const float*)d_in[1];
    if (in_sizes[0] == DIM_D * DIM_L) {
        x = (const float*)d_in[1];
        w = (const float*)d_in[0];
    }
    float* out = (float*)d_out;

    float *G, *Bb, *U0, *U1;
    __nv_bfloat16 *A0h, *A0l, *A1h, *A1l, *Gh, *Gl;
    cudaGetSymbolAddress((void**)&G,   g_G);
    cudaGetSymbolAddress((void**)&Bb,  g_B);
    cudaGetSymbolAddress((void**)&U0,  g_U0);
    cudaGetSymbolAddress((void**)&U1,  g_U1);
    cudaGetSymbolAddress((void**)&A0h, g_A0h);
    cudaGetSymbolAddress((void**)&A0l, g_A0l);
    cudaGetSymbolAddress((void**)&A1h, g_A1h);
    cudaGetSymbolAddress((void**)&A1l, g_A1l);
    cudaGetSymbolAddress((void**)&Gh,  g_Gh);
    cudaGetSymbolAddress((void**)&Gl,  g_Gl);

    const dim3 blk(256);

    // g = W^T W - I
    gemm_k<2, 0, 1, false><<<dim3(8, 8), blk>>>(
        w, w, G, DIM_L, DIM_L, DIM_D, DIM_L, DIM_L);

    // b = X W
    gemm_k<0, 0, 0, false><<<dim3(8, 128), blk>>>(
        x, w, Bb, NUM_B, DIM_L, DIM_D, DIM_D, DIM_L);

    // split G into bf16 hi/lo
    split_kernel<<<(DIM_L * DIM_L) / 4 / 256, 256>>>(G, Gh, Gl);

    // step 1: u = 0.1*b, a = thresh(u) split
    init_u_kernel<<<(NUM_B * DIM_L) / 4 / 256, 256>>>(Bb, U0, A0h, A0l);

    // steps 2..49 on tensor pipe (mma.sync bf16x3)
    float* uin = U0;  float* uout = U1;
    __nv_bfloat16 *ahi = A0h, *alo = A0l, *ohi = A1h, *olo = A1l;
    for (int s = 0; s < 48; s++) {
        lca_step_mma<<<dim3(8, 128), 256>>>(
            ahi, alo, Gh, Gl, uin, Bb, uout, ohi, olo);
        float* tu = uin; uin = uout; uout = tu;
        __nv_bfloat16* t;
        t = ahi; ahi = ohi; ohi = t;
        t = alo; alo = olo; olo = t;
    }

    // recon = thresh(u_final) @ W^T
    gemm_k<1, 1, 0, true><<<dim3(7, 128), blk>>>(
        uin, w, out, NUM_B, DIM_D, DIM_L, DIM_L, DIM_L);
}

// round 4
// speedup vs baseline: 2.1616x; 1.0330x over previous
#include <cuda_runtime.h>
#include <cuda_bf16.h>
#include <cstdint>

// Problem constants
#define NUM_B 16384
#define DIM_D 784
#define DIM_L 1024
#define LAMBDA 0.3f
#define STEPSZ 0.1f

// ---------------- scratch (__device__ globals; no allocs allowed) ----------
__device__ float g_G [DIM_L * DIM_L];
__device__ float g_B [(size_t)NUM_B * DIM_L];
__device__ float g_U0[(size_t)NUM_B * DIM_L];
__device__ float g_U1[(size_t)NUM_B * DIM_L];
__device__ __nv_bfloat16 g_A0h[(size_t)NUM_B * DIM_L];
__device__ __nv_bfloat16 g_A0l[(size_t)NUM_B * DIM_L];
__device__ __nv_bfloat16 g_A1h[(size_t)NUM_B * DIM_L];
__device__ __nv_bfloat16 g_A1l[(size_t)NUM_B * DIM_L];
__device__ __nv_bfloat16 g_Gh[DIM_L * DIM_L];
__device__ __nv_bfloat16 g_Gl[DIM_L * DIM_L];

__device__ __forceinline__ float lca_thresh(float x) {
    return x > LAMBDA ? x - LAMBDA : 0.0f;
}

// ---------------- baseline-ISA tensor helpers (sm_80+, valid on sm_103) ----
__device__ __forceinline__ uint32_t smem_u32(const void* p) {
    uint32_t a;
    asm("{ .reg .u64 t; cvta.to.shared.u64 t, %1; cvt.u32.u64 %0, t; }"
        : "=r"(a) : "l"(p));
    return a;
}
__device__ __forceinline__ void cp16(uint32_t dst, const void* src) {
    asm volatile("cp.async.cg.shared.global [%0], [%1], 16;"
                 :: "r"(dst), "l"(src) : "memory");
}
__device__ __forceinline__ void cp_commit() {
    asm volatile("cp.async.commit_group;" ::: "memory");
}
template <int N>
__device__ __forceinline__ void cp_wait() {
    asm volatile("cp.async.wait_group %0;" :: "n"(N) : "memory");
}
__device__ __forceinline__ void ldsm_x4(uint32_t* r, uint32_t a) {
    asm volatile("ldmatrix.sync.aligned.m8n8.x4.shared.b16 {%0,%1,%2,%3}, [%4];"
                 : "=r"(r[0]), "=r"(r[1]), "=r"(r[2]), "=r"(r[3]) : "r"(a));
}
__device__ __forceinline__ void ldsm_x2(uint32_t* r, uint32_t a) {
    asm volatile("ldmatrix.sync.aligned.m8n8.x2.shared.b16 {%0,%1}, [%2];"
                 : "=r"(r[0]), "=r"(r[1]) : "r"(a));
}
__device__ __forceinline__ void mma_bf16(float* c, const uint32_t* a, const uint32_t* b) {
    asm volatile(
        "mma.sync.aligned.m16n8k16.row.col.f32.bf16.bf16.f32 "
        "{%0,%1,%2,%3}, {%4,%5,%6,%7}, {%8,%9}, {%0,%1,%2,%3};"
        : "+f"(c[0]), "+f"(c[1]), "+f"(c[2]), "+f"(c[3])
        : "r"(a[0]), "r"(a[1]), "r"(a[2]), "r"(a[3]), "r"(b[0]), "r"(b[1]));
}

// ============================================================================
// Pipelined LCA step:  D = a@G (bf16x3),  u' = 0.9u + 0.1b - 0.1D,
// fused write of u' (fp32) and thresh(u') hi/lo (bf16).
// Grid (8,128), 256 threads. 2-stage cp.async pipeline, 80KB dyn smem.
// ============================================================================
#define BK   32
#define PAD  40                       // bf16/row: 80B, ldmatrix conflict-free
#define TILE_B   (128 * PAD * 2)      // 10240 B per tile
#define STAGE_B  (4 * TILE_B)         // 40960 B per stage
#define STEP_SMEM (2 * STAGE_B)       // 81920 B
#define NC   (DIM_L / BK)             // 32 chunks

__global__ __launch_bounds__(256, 2)
void lca_step_mma(const __nv_bfloat16* __restrict__ Ahi,
                  const __nv_bfloat16* __restrict__ Alo,
                  const __nv_bfloat16* __restrict__ Ghi,
                  const __nv_bfloat16* __restrict__ Glo,
                  const float* __restrict__ Uin,
                  const float* __restrict__ Bex,
                  float* __restrict__ Uout,
                  __nv_bfloat16* __restrict__ AhiOut,
                  __nv_bfloat16* __restrict__ AloOut)
{
    extern __shared__ __align__(16) char dsmem[];
    const uint32_t sb = smem_u32(dsmem);

    const int tid  = threadIdx.x;
    const int lane = tid & 31;
    const int wid  = tid >> 5;
    const int wy   = wid >> 2;   // 0..1 (M)
    const int wx   = wid & 3;    // 0..3 (N)
    const int m0   = blockIdx.y * 128;
    const int n0   = blockIdx.x * 128;

    // ldmatrix lane addressing
    const int a_row = lane & 15;
    const int a_kh  = lane >> 4;
    const int b_row = lane & 7;
    const int b_kh  = (lane >> 3) & 1;

    // per-lane byte offsets within a tile (add kk*2 + stage base)
    uint32_t aoffs[4], boffs[4];
    #pragma unroll
    for (int mi = 0; mi < 4; mi++)
        aoffs[mi] = (uint32_t)((wy * 64 + mi * 16 + a_row) * PAD + a_kh * 8) * 2;
    #pragma unroll
    for (int ni = 0; ni < 4; ni++)
        boffs[ni] = (uint32_t)((wx * 32 + ni * 8 + b_row) * PAD + b_kh * 8) * 2;

    // global-load mapping: 2 x 16B per thread per tile
    const int v0row = tid >> 2;
    const int v0kq  = (tid & 3) * 8;
    const uint32_t s0 = (uint32_t)(v0row * PAD + v0kq) * 2;
    const uint32_t s1 = (uint32_t)((v0row + 64) * PAD + v0kq) * 2;

    float acc[4][4][4];
    #pragma unroll
    for (int i = 0; i < 4; i++)
        #pragma unroll
        for (int j = 0; j < 4; j++)
            #pragma unroll
            for (int q = 0; q < 4; q++) acc[i][j][q] = 0.0f;

    // issue one chunk's 8 cp.async into a stage
    auto issue = [&](int c, int stage) {
        const int k0 = c * BK;
        const uint32_t base = sb + stage * STAGE_B;
        const size_t ga0 = (size_t)(m0 + v0row) * DIM_L + k0 + v0kq;
        const size_t ga1 = ga0 + (size_t)64 * DIM_L;
        const size_t gg0 = (size_t)(n0 + v0row) * DIM_L + k0 + v0kq;
        const size_t gg1 = gg0 + (size_t)64 * DIM_L;
        cp16(base + 0 * TILE_B + s0, Ahi + ga0);
        cp16(base + 0 * TILE_B + s1, Ahi + ga1);
        cp16(base + 1 * TILE_B + s0, Alo + ga0);
        cp16(base + 1 * TILE_B + s1, Alo + ga1);
        cp16(base + 2 * TILE_B + s0, Ghi + gg0);
        cp16(base + 2 * TILE_B + s1, Ghi + gg1);
        cp16(base + 3 * TILE_B + s0, Glo + gg0);
        cp16(base + 3 * TILE_B + s1, Glo + gg1);
        cp_commit();
    };

    issue(0, 0);

    #pragma unroll 1
    for (int c = 0; c < NC; c++) {
        if (c + 1 < NC) {
            issue(c + 1, (c + 1) & 1);
            cp_wait<1>();
        } else {
            cp_wait<0>();
        }
        __syncthreads();

        const uint32_t base = sb + (c & 1) * STAGE_B;
        const uint32_t uAh = base + 0 * TILE_B;
        const uint32_t uAl = base + 1 * TILE_B;
        const uint32_t uGh = base + 2 * TILE_B;
        const uint32_t uGl = base + 3 * TILE_B;

        #pragma unroll
        for (int kk = 0; kk < BK; kk += 16) {
            uint32_t bfh[4][2], bfl[4][2];
            uint32_t af[4][4];
            const uint32_t kb = (uint32_t)kk * 2;

            #pragma unroll
            for (int ni = 0; ni < 4; ni++) {
                ldsm_x2(bfh[ni], uGh + boffs[ni] + kb);
                ldsm_x2(bfl[ni], uGl + boffs[ni] + kb);
            }
            // A = a_hi : multiply vs G_hi and G_lo
            #pragma unroll
            for (int mi = 0; mi < 4; mi++)
                ldsm_x4(af[mi], uAh + aoffs[mi] + kb);
            #pragma unroll
            for (int mi = 0; mi < 4; mi++)
                #pragma unroll
                for (int ni = 0; ni < 4; ni++)
                    mma_bf16(acc[mi][ni], af[mi], bfh[ni]);
            #pragma unroll
            for (int mi = 0; mi < 4; mi++)
                #pragma unroll
                for (int ni = 0; ni < 4; ni++)
                    mma_bf16(acc[mi][ni], af[mi], bfl[ni]);
            // A = a_lo : multiply vs G_hi
            #pragma unroll
            for (int mi = 0; mi < 4; mi++)
                ldsm_x4(af[mi], uAl + aoffs[mi] + kb);
            #pragma unroll
            for (int mi = 0; mi < 4; mi++)
                #pragma unroll
                for (int ni = 0; ni < 4; ni++)
                    mma_bf16(acc[mi][ni], af[mi], bfh[ni]);
        }
        __syncthreads();
    }

    // ---------------- fused epilogue ----------------
    const int g  = lane >> 2;
    const int tg = lane & 3;
    #pragma unroll
    for (int mi = 0; mi < 4; mi++) {
        #pragma unroll
        for (int ni = 0; ni < 4; ni++) {
            const int r0 = m0 + wy * 64 + mi * 16 + g;
            const int c0 = n0 + wx * 32 + ni * 8 + tg * 2;
            #pragma unroll
            for (int h = 0; h < 2; h++) {
                const size_t idx = (size_t)(r0 + h * 8) * DIM_L + c0;
                const float d0 = acc[mi][ni][h * 2 + 0];
                const float d1 = acc[mi][ni][h * 2 + 1];
                const float2 u2 = *(const float2*)(Uin + idx);
                const float2 b2 = *(const float2*)(Bex + idx);
                float vx = (1.0f - STEPSZ) * u2.x + STEPSZ * b2.x - STEPSZ * d0;
                float vy = (1.0f - STEPSZ) * u2.y + STEPSZ * b2.y - STEPSZ * d1;
                *(float2*)(Uout + idx) = make_float2(vx, vy);
                const float a0 = lca_thresh(vx), a1 = lca_thresh(vy);
                const __nv_bfloat16 h0 = __float2bfloat16(a0);
                const __nv_bfloat16 h1 = __float2bfloat16(a1);
                const __nv_bfloat16 l0 = __float2bfloat16(a0 - __bfloat162float(h0));
                const __nv_bfloat16 l1 = __float2bfloat16(a1 - __bfloat162float(h1));
                *(uint32_t*)(AhiOut + idx) =
                    ((uint32_t)__bfloat16_as_ushort(h1) << 16) | __bfloat16_as_ushort(h0);
                *(uint32_t*)(AloOut + idx) =
                    ((uint32_t)__bfloat16_as_ushort(l1) << 16) | __bfloat16_as_ushort(l0);
            }
        }
    }
}

// ============================================================================
// SIMT fp32 GEMM (R1) for g, b, recon
// ============================================================================
template<int OPA, int OPB, int EPI, bool NB>
__global__ __launch_bounds__(256, 2)
void gemm_k(const float* __restrict__ A, const float* __restrict__ Bm,
            float* __restrict__ C,
            int M, int N, int K, int lda, int ldb)
{
    __shared__ float As[16][128];
    __shared__ float Bs[16][128];

    const int tid = threadIdx.x;
    const int m0 = blockIdx.y * 128;
    const int n0 = blockIdx.x * 128;
    const int tx4 = (tid & 15) * 4;
    const int ty4 = (tid >> 4) * 4;

    float acc[8][8];
    #pragma unroll
    for (int i = 0; i < 8; i++)
        #pragma unroll
        for (int j = 0; j < 8; j++) acc[i][j] = 0.0f;

    for (int k0 = 0; k0 < K; k0 += 16) {
        if (OPA == 0 || OPA == 1) {
            const int m  = tid & 127;
            const int kq = (tid >> 7) * 8;
            const float* src = A + (size_t)(m0 + m) * lda + k0 + kq;
            float4 v0 = *(const float4*)(src);
            float4 v1 = *(const float4*)(src + 4);
            if (OPA == 1) {
                v0.x = lca_thresh(v0.x); v0.y = lca_thresh(v0.y);
                v0.z = lca_thresh(v0.z); v0.w = lca_thresh(v0.w);
                v1.x = lca_thresh(v1.x); v1.y = lca_thresh(v1.y);
                v1.z = lca_thresh(v1.z); v1.w = lca_thresh(v1.w);
            }
            As[kq + 0][m] = v0.x; As[kq + 1][m] = v0.y;
            As[kq + 2][m] = v0.z; As[kq + 3][m] = v0.w;
            As[kq + 4][m] = v1.x; As[kq + 5][m] = v1.y;
            As[kq + 6][m] = v1.z; As[kq + 7][m] = v1.w;
        } else {
            const int k  = tid >> 4;
            const int mq = (tid & 15) * 8;
            const float* src = A + (size_t)(k0 + k) * lda + m0 + mq;
            *(float4*)&As[k][mq]     = *(const float4*)(src);
            *(float4*)&As[k][mq + 4] = *(const float4*)(src + 4);
        }

        if (OPB == 0) {
            const int k  = tid >> 4;
            const int nq = (tid & 15) * 8;
            const float* src = Bm + (size_t)(k0 + k) * ldb + n0 + nq;
            *(float4*)&Bs[k][nq]     = *(const float4*)(src);
            *(float4*)&Bs[k][nq + 4] = *(const float4*)(src + 4);
        } else {
            const int n  = tid & 127;
            const int kq = (tid >> 7) * 8;
            float4 v0 = make_float4(0.f, 0.f, 0.f, 0.f);
            float4 v1 = v0;
            if (!NB || (n0 + n) < N) {
                const float* src = Bm + (size_t)(n0 + n) * ldb + k0 + kq;
                v0 = *(const float4*)(src);
                v1 = *(const float4*)(src + 4);
            }
            Bs[kq + 0][n] = v0.x; Bs[kq + 1][n] = v0.y;
            Bs[kq + 2][n] = v0.z; Bs[kq + 3][n] = v0.w;
            Bs[kq + 4][n] = v1.x; Bs[kq + 5][n] = v1.y;
            Bs[kq + 6][n] = v1.z; Bs[kq + 7][n] = v1.w;
        }

        __syncthreads();

        #pragma unroll
        for (int kk = 0; kk < 16; kk++) {
            float4 a0 = *(const float4*)&As[kk][ty4];
            float4 a1 = *(const float4*)&As[kk][ty4 + 64];
            float4 b0 = *(const float4*)&Bs[kk][tx4];
            float4 b1 = *(const float4*)&Bs[kk][tx4 + 64];
            float ar[8] = {a0.x, a0.y, a0.z, a0.w, a1.x, a1.y, a1.z, a1.w};
            float br[8] = {b0.x, b0.y, b0.z, b0.w, b1.x, b1.y, b1.z, b1.w};
            #pragma unroll
            for (int i = 0; i < 8; i++)
                #pragma unroll
                for (int j = 0; j < 8; j++)
                    acc[i][j] += ar[i] * br[j];
        }

        __syncthreads();
    }

    #pragma unroll
    for (int ih = 0; ih < 2; ih++) {
        #pragma unroll
        for (int ii = 0; ii < 4; ii++) {
            const int row = m0 + ih * 64 + ty4 + ii;
            #pragma unroll
            for (int jh = 0; jh < 2; jh++) {
                const int col = n0 + jh * 64 + tx4;
                if (NB && col >= N) continue;
                const size_t idx = (size_t)row * N + col;
                float4 v;
                v.x = acc[ih * 4 + ii][jh * 4 + 0];
                v.y = acc[ih * 4 + ii][jh * 4 + 1];
                v.z = acc[ih * 4 + ii][jh * 4 + 2];
                v.w = acc[ih * 4 + ii][jh * 4 + 3];
                if (EPI == 1) {
                    if (row == col + 0) v.x -= 1.0f;
                    if (row == col + 1) v.y -= 1.0f;
                    if (row == col + 2) v.z -= 1.0f;
                    if (row == col + 3) v.w -= 1.0f;
                }
                *(float4*)&C[idx] = v;
            }
        }
    }
}

// split fp32 -> bf16 hi/lo
__global__ void split_kernel(const float* __restrict__ src,
                             __nv_bfloat16* __restrict__ hi,
                             __nv_bfloat16* __restrict__ lo)
{
    const size_t i = ((size_t)blockIdx.x * blockDim.x + threadIdx.x) * 4;
    const float4 v = *(const float4*)(src + i);
    uint32_t hp[2], lp[2];
    const __nv_bfloat16 h0 = __float2bfloat16(v.x), h1 = __float2bfloat16(v.y);
    const __nv_bfloat16 h2 = __float2bfloat16(v.z), h3 = __float2bfloat16(v.w);
    const __nv_bfloat16 l0 = __float2bfloat16(v.x - __bfloat162float(h0));
    const __nv_bfloat16 l1 = __float2bfloat16(v.y - __bfloat162float(h1));
    const __nv_bfloat16 l2 = __float2bfloat16(v.z - __bfloat162float(h2));
    const __nv_bfloat16 l3 = __float2bfloat16(v.w - __bfloat162float(h3));
    hp[0] = ((uint32_t)__bfloat16_as_ushort(h1) << 16) | __bfloat16_as_ushort(h0);
    hp[1] = ((uint32_t)__bfloat16_as_ushort(h3) << 16) | __bfloat16_as_ushort(h2);
    lp[0] = ((uint32_t)__bfloat16_as_ushort(l1) << 16) | __bfloat16_as_ushort(l0);
    lp[1] = ((uint32_t)__bfloat16_as_ushort(l3) << 16) | __bfloat16_as_ushort(l2);
    *(uint2*)(hi + i) = *(const uint2*)hp;
    *(uint2*)(lo + i) = *(const uint2*)lp;
}

// u1 = 0.1*b; a1 = thresh(u1) split hi/lo
__global__ void init_u_kernel(const float* __restrict__ b, float* __restrict__ u,
                              __nv_bfloat16* __restrict__ hi,
                              __nv_bfloat16* __restrict__ lo)
{
    const size_t i = ((size_t)blockIdx.x * blockDim.x + threadIdx.x) * 4;
    float4 v = *(const float4*)(b + i);
    v.x *= STEPSZ; v.y *= STEPSZ; v.z *= STEPSZ; v.w *= STEPSZ;
    *(float4*)(u + i) = v;
    const float a0 = lca_thresh(v.x), a1 = lca_thresh(v.y);
    const float a2 = lca_thresh(v.z), a3 = lca_thresh(v.w);
    uint32_t hp[2], lp[2];
    const __nv_bfloat16 h0 = __float2bfloat16(a0), h1 = __float2bfloat16(a1);
    const __nv_bfloat16 h2 = __float2bfloat16(a2), h3 = __float2bfloat16(a3);
    const __nv_bfloat16 l0 = __float2bfloat16(a0 - __bfloat162float(h0));
    const __nv_bfloat16 l1 = __float2bfloat16(a1 - __bfloat162float(h1));
    const __nv_bfloat16 l2 = __float2bfloat16(a2 - __bfloat162float(h2));
    const __nv_bfloat16 l3 = __float2bfloat16(a3 - __bfloat162float(h3));
    hp[0] = ((uint32_t)__bfloat16_as_ushort(h1) << 16) | __bfloat16_as_ushort(h0);
    hp[1] = ((uint32_t)__bfloat16_as_ushort(h3) << 16) | __bfloat16_as_ushort(h2);
    lp[0] = ((uint32_t)__bfloat16_as_ushort(l1) << 16) | __bfloat16_as_ushort(l0);
    lp[1] = ((uint32_t)__bfloat16_as_ushort(l3) << 16) | __bfloat16_as_ushort(l2);
    *(uint2*)(hi + i) = *(const uint2*)hp;
    *(uint2*)(lo + i) = *(const uint2*)lp;
}

// ============================================================================
extern "C" void kernel_launch(void* const* d_in, const int* in_sizes, int n_in,
                              void* d_out, int out_size) {
    (void)n_in; (void)out_size;

    const float* x = (const float*)d_in[0];
    const float* w = (const float*)d_in[1];
    if (in_sizes[0] == DIM_D * DIM_L) {
        x = (const float*)d_in[1];
        w = (const float*)d_in[0];
    }
    float* out = (float*)d_out;

    float *G, *Bb, *U0, *U1;
    __nv_bfloat16 *A0h, *A0l, *A1h, *A1l, *Gh, *Gl;
    cudaGetSymbolAddress((void**)&G,   g_G);
    cudaGetSymbolAddress((void**)&Bb,  g_B);
    cudaGetSymbolAddress((void**)&U0,  g_U0);
    cudaGetSymbolAddress((void**)&U1,  g_U1);
    cudaGetSymbolAddress((void**)&A0h, g_A0h);
    cudaGetSymbolAddress((void**)&A0l, g_A0l);
    cudaGetSymbolAddress((void**)&A1h, g_A1h);
    cudaGetSymbolAddress((void**)&A1l, g_A1l);
    cudaGetSymbolAddress((void**)&Gh,  g_Gh);
    cudaGetSymbolAddress((void**)&Gl,  g_Gl);

    cudaFuncSetAttribute(lca_step_mma,
                         cudaFuncAttributeMaxDynamicSharedMemorySize, STEP_SMEM);

    const dim3 blk(256);

    // g = W^T W - I
    gemm_k<2, 0, 1, false><<<dim3(8, 8), blk>>>(
        w, w, G, DIM_L, DIM_L, DIM_D, DIM_L, DIM_L);

    // b = X W
    gemm_k<0, 0, 0, false><<<dim3(8, 128), blk>>>(
        x, w, Bb, NUM_B, DIM_L, DIM_D, DIM_D, DIM_L);

    // split G into bf16 hi/lo
    split_kernel<<<(DIM_L * DIM_L) / 4 / 256, 256>>>(G, Gh, Gl);

    // step 1: u = 0.1*b, a = thresh(u) split
    init_u_kernel<<<(NUM_B * DIM_L) / 4 / 256, 256>>>(Bb, U0, A0h, A0l);

    // steps 2..49 on tensor pipe (pipelined mma.sync bf16x3)
    float* uin = U0;  float* uout = U1;
    __nv_bfloat16 *ahi = A0h, *alo = A0l, *ohi = A1h, *olo = A1l;
    for (int s = 0; s < 48; s++) {
        lca_step_mma<<<dim3(8, 128), 256, STEP_SMEM>>>(
            ahi, alo, Gh, Gl, uin, Bb, uout, ohi, olo);
        float* tu = uin; uin = uout; uout = tu;
        __nv_bfloat16* t;
        t = ahi; ahi = ohi; ohi = t;
        t = alo; alo = olo; olo = t;
    }

    // recon = thresh(u_final) @ W^T
    gemm_k<1, 1, 0, true><<<dim3(7, 128), blk>>>(
        uin, w, out, NUM_B, DIM_D, DIM_L, DIM_L, DIM_L);
}

// round 5
// speedup vs baseline: 2.7886x; 1.2901x over previous
#include <cuda_runtime.h>
#include <cuda_fp16.h>
#include <cstdint>

// Problem constants
#define NUM_B 16384
#define DIM_D 784
#define DIM_L 1024
#define LAMBDA 0.3f
#define STEPSZ 0.1f

// ---------------- scratch (__device__ globals; no allocs allowed) ----------
__device__ float g_G [DIM_L * DIM_L];
__device__ float g_B [(size_t)NUM_B * DIM_L];
__device__ float g_U0[(size_t)NUM_B * DIM_L];
__device__ float g_U1[(size_t)NUM_B * DIM_L];
__device__ __half g_A0h[(size_t)NUM_B * DIM_L];   // a_hi ping (fp16)
__device__ __half g_A0l[(size_t)NUM_B * DIM_L];   // a_lo ping
__device__ __half g_A1h[(size_t)NUM_B * DIM_L];   // a_hi pong
__device__ __half g_A1l[(size_t)NUM_B * DIM_L];   // a_lo pong
__device__ __half g_Gh[DIM_L * DIM_L];            // fp16(G)

__device__ __forceinline__ float lca_thresh(float x) {
    return x > LAMBDA ? x - LAMBDA : 0.0f;
}

// ---------------- baseline-ISA tensor helpers (sm_80+, valid on sm_103) ----
__device__ __forceinline__ uint32_t smem_u32(const void* p) {
    uint32_t a;
    asm("{ .reg .u64 t; cvta.to.shared.u64 t, %1; cvt.u32.u64 %0, t; }"
        : "=r"(a) : "l"(p));
    return a;
}
__device__ __forceinline__ void cp16(uint32_t dst, const void* src) {
    asm volatile("cp.async.cg.shared.global [%0], [%1], 16;"
                 :: "r"(dst), "l"(src) : "memory");
}
__device__ __forceinline__ void cp_commit() {
    asm volatile("cp.async.commit_group;" ::: "memory");
}
template <int N>
__device__ __forceinline__ void cp_wait() {
    asm volatile("cp.async.wait_group %0;" :: "n"(N) : "memory");
}
__device__ __forceinline__ void ldsm_x4(uint32_t* r, uint32_t a) {
    asm volatile("ldmatrix.sync.aligned.m8n8.x4.shared.b16 {%0,%1,%2,%3}, [%4];"
                 : "=r"(r[0]), "=r"(r[1]), "=r"(r[2]), "=r"(r[3]) : "r"(a));
}
__device__ __forceinline__ void ldsm_x2(uint32_t* r, uint32_t a) {
    asm volatile("ldmatrix.sync.aligned.m8n8.x2.shared.b16 {%0,%1}, [%2];"
                 : "=r"(r[0]), "=r"(r[1]) : "r"(a));
}
__device__ __forceinline__ void mma_f16(float* c, const uint32_t* a, const uint32_t* b) {
    asm volatile(
        "mma.sync.aligned.m16n8k16.row.col.f32.f16.f16.f32 "
        "{%0,%1,%2,%3}, {%4,%5,%6,%7}, {%8,%9}, {%0,%1,%2,%3};"
        : "+f"(c[0]), "+f"(c[1]), "+f"(c[2]), "+f"(c[3])
        : "r"(a[0]), "r"(a[1]), "r"(a[2]), "r"(a[3]), "r"(b[0]), "r"(b[1]));
}

// ============================================================================
// Pipelined LCA step (fp16 2-product):
//   D = a_hi@G_h + a_lo@G_h,  u' = 0.9u + 0.1b - 0.1D,
//   fused write of u' (fp32) and thresh(u') hi/lo (fp16).
// Grid (8,128), 256 threads. 2-stage cp.async pipeline, 60KB dyn smem.
// ============================================================================
#define BK   32
#define PAD  40                       // fp16/row: 80B, ldmatrix conflict-free
#define TILE_B    (128 * PAD * 2)     // 10240 B per tile
#define STAGE_B   (3 * TILE_B)        // 30720 B per stage
#define STEP_SMEM (2 * STAGE_B)       // 61440 B
#define NC   (DIM_L / BK)             // 32 chunks

__global__ __launch_bounds__(256, 2)
void lca_step_mma(const __half* __restrict__ Ahi,
                  const __half* __restrict__ Alo,
                  const __half* __restrict__ Gh,
                  const float* __restrict__ Uin,
                  const float* __restrict__ Bex,
                  float* __restrict__ Uout,
                  __half* __restrict__ AhiOut,
                  __half* __restrict__ AloOut)
{
    extern __shared__ __align__(16) char dsmem[];
    const uint32_t sb = smem_u32(dsmem);

    const int tid  = threadIdx.x;
    const int lane = tid & 31;
    const int wid  = tid >> 5;
    const int wy   = wid >> 2;   // 0..1 (M)
    const int wx   = wid & 3;    // 0..3 (N)
    const int m0   = blockIdx.y * 128;
    const int n0   = blockIdx.x * 128;

    // ldmatrix lane addressing
    const int a_row = lane & 15;
    const int a_kh  = lane >> 4;
    const int b_row = lane & 7;
    const int b_kh  = (lane >> 3) & 1;

    uint32_t aoffs[4], boffs[4];
    #pragma unroll
    for (int mi = 0; mi < 4; mi++)
        aoffs[mi] = (uint32_t)((wy * 64 + mi * 16 + a_row) * PAD + a_kh * 8) * 2;
    #pragma unroll
    for (int ni = 0; ni < 4; ni++)
        boffs[ni] = (uint32_t)((wx * 32 + ni * 8 + b_row) * PAD + b_kh * 8) * 2;

    // global-load mapping: 2 x 16B per thread per tile
    const int v0row = tid >> 2;
    const int v0kq  = (tid & 3) * 8;
    const uint32_t s0 = (uint32_t)(v0row * PAD + v0kq) * 2;
    const uint32_t s1 = (uint32_t)((v0row + 64) * PAD + v0kq) * 2;

    float acc[4][4][4];
    #pragma unroll
    for (int i = 0; i < 4; i++)
        #pragma unroll
        for (int j = 0; j < 4; j++)
            #pragma unroll
            for (int q = 0; q < 4; q++) acc[i][j][q] = 0.0f;

    auto issue = [&](int c, int stage) {
        const int k0 = c * BK;
        const uint32_t base = sb + stage * STAGE_B;
        const size_t ga0 = (size_t)(m0 + v0row) * DIM_L + k0 + v0kq;
        const size_t ga1 = ga0 + (size_t)64 * DIM_L;
        const size_t gg0 = (size_t)(n0 + v0row) * DIM_L + k0 + v0kq;
        const size_t gg1 = gg0 + (size_t)64 * DIM_L;
        cp16(base + 0 * TILE_B + s0, Ahi + ga0);
        cp16(base + 0 * TILE_B + s1, Ahi + ga1);
        cp16(base + 1 * TILE_B + s0, Alo + ga0);
        cp16(base + 1 * TILE_B + s1, Alo + ga1);
        cp16(base + 2 * TILE_B + s0, Gh + gg0);
        cp16(base + 2 * TILE_B + s1, Gh + gg1);
        cp_commit();
    };

    issue(0, 0);

    #pragma unroll 1
    for (int c = 0; c < NC; c++) {
        if (c + 1 < NC) {
            issue(c + 1, (c + 1) & 1);
            cp_wait<1>();
        } else {
            cp_wait<0>();
        }
        __syncthreads();

        const uint32_t base = sb + (c & 1) * STAGE_B;
        const uint32_t uAh = base + 0 * TILE_B;
        const uint32_t uAl = base + 1 * TILE_B;
        const uint32_t uGh = base + 2 * TILE_B;

        #pragma unroll
        for (int kk = 0; kk < BK; kk += 16) {
            uint32_t bfh[4][2];
            uint32_t af[4][4];
            const uint32_t kb = (uint32_t)kk * 2;

            #pragma unroll
            for (int ni = 0; ni < 4; ni++)
                ldsm_x2(bfh[ni], uGh + boffs[ni] + kb);
            // a_hi @ G_h
            #pragma unroll
            for (int mi = 0; mi < 4; mi++)
                ldsm_x4(af[mi], uAh + aoffs[mi] + kb);
            #pragma unroll
            for (int mi = 0; mi < 4; mi++)
                #pragma unroll
                for (int ni = 0; ni < 4; ni++)
                    mma_f16(acc[mi][ni], af[mi], bfh[ni]);
            // a_lo @ G_h
            #pragma unroll
            for (int mi = 0; mi < 4; mi++)
                ldsm_x4(af[mi], uAl + aoffs[mi] + kb);
            #pragma unroll
            for (int mi = 0; mi < 4; mi++)
                #pragma unroll
                for (int ni = 0; ni < 4; ni++)
                    mma_f16(acc[mi][ni], af[mi], bfh[ni]);
        }
        __syncthreads();
    }

    // ---------------- fused epilogue ----------------
    const int g  = lane >> 2;
    const int tg = lane & 3;
    #pragma unroll
    for (int mi = 0; mi < 4; mi++) {
        #pragma unroll
        for (int ni = 0; ni < 4; ni++) {
            const int r0 = m0 + wy * 64 + mi * 16 + g;
            const int c0 = n0 + wx * 32 + ni * 8 + tg * 2;
            #pragma unroll
            for (int h = 0; h < 2; h++) {
                const size_t idx = (size_t)(r0 + h * 8) * DIM_L + c0;
                const float d0 = acc[mi][ni][h * 2 + 0];
                const float d1 = acc[mi][ni][h * 2 + 1];
                const float2 u2 = *(const float2*)(Uin + idx);
                const float2 b2 = *(const float2*)(Bex + idx);
                float vx = (1.0f - STEPSZ) * u2.x + STEPSZ * b2.x - STEPSZ * d0;
                float vy = (1.0f - STEPSZ) * u2.y + STEPSZ * b2.y - STEPSZ * d1;
                *(float2*)(Uout + idx) = make_float2(vx, vy);
                const float a0 = lca_thresh(vx), a1 = lca_thresh(vy);
                const __half h0 = __float2half_rn(a0);
                const __half h1 = __float2half_rn(a1);
                const __half l0 = __float2half_rn(a0 - __half2float(h0));
                const __half l1 = __float2half_rn(a1 - __half2float(h1));
                *(uint32_t*)(AhiOut + idx) =
                    ((uint32_t)__half_as_ushort(h1) << 16) | __half_as_ushort(h0);
                *(uint32_t*)(AloOut + idx) =
                    ((uint32_t)__half_as_ushort(l1) << 16) | __half_as_ushort(l0);
            }
        }
    }
}

// ============================================================================
// SIMT fp32 GEMM (R1) for g, b, recon
// ============================================================================
template<int OPA, int OPB, int EPI, bool NB>
__global__ __launch_bounds__(256, 2)
void gemm_k(const float* __restrict__ A, const float* __restrict__ Bm,
            float* __restrict__ C,
            int M, int N, int K, int lda, int ldb)
{
    __shared__ float As[16][128];
    __shared__ float Bs[16][128];

    const int tid = threadIdx.x;
    const int m0 = blockIdx.y * 128;
    const int n0 = blockIdx.x * 128;
    const int tx4 = (tid & 15) * 4;
    const int ty4 = (tid >> 4) * 4;

    float acc[8][8];
    #pragma unroll
    for (int i = 0; i < 8; i++)
        #pragma unroll
        for (int j = 0; j < 8; j++) acc[i][j] = 0.0f;

    for (int k0 = 0; k0 < K; k0 += 16) {
        if (OPA == 0 || OPA == 1) {
            const int m  = tid & 127;
            const int kq = (tid >> 7) * 8;
            const float* src = A + (size_t)(m0 + m) * lda + k0 + kq;
            float4 v0 = *(const float4*)(src);
            float4 v1 = *(const float4*)(src + 4);
            if (OPA == 1) {
                v0.x = lca_thresh(v0.x); v0.y = lca_thresh(v0.y);
                v0.z = lca_thresh(v0.z); v0.w = lca_thresh(v0.w);
                v1.x = lca_thresh(v1.x); v1.y = lca_thresh(v1.y);
                v1.z = lca_thresh(v1.z); v1.w = lca_thresh(v1.w);
            }
            As[kq + 0][m] = v0.x; As[kq + 1][m] = v0.y;
            As[kq + 2][m] = v0.z; As[kq + 3][m] = v0.w;
            As[kq + 4][m] = v1.x; As[kq + 5][m] = v1.y;
            As[kq + 6][m] = v1.z; As[kq + 7][m] = v1.w;
        } else {
            const int k  = tid >> 4;
            const int mq = (tid & 15) * 8;
            const float* src = A + (size_t)(k0 + k) * lda + m0 + mq;
            *(float4*)&As[k][mq]     = *(const float4*)(src);
            *(float4*)&As[k][mq + 4] = *(const float4*)(src + 4);
        }

        if (OPB == 0) {
            const int k  = tid >> 4;
            const int nq = (tid & 15) * 8;
            const float* src = Bm + (size_t)(k0 + k) * ldb + n0 + nq;
            *(float4*)&Bs[k][nq]     = *(const float4*)(src);
            *(float4*)&Bs[k][nq + 4] = *(const float4*)(src + 4);
        } else {
            const int n  = tid & 127;
            const int kq = (tid >> 7) * 8;
            float4 v0 = make_float4(0.f, 0.f, 0.f, 0.f);
            float4 v1 = v0;
            if (!NB || (n0 + n) < N) {
                const float* src = Bm + (size_t)(n0 + n) * ldb + k0 + kq;
                v0 = *(const float4*)(src);
                v1 = *(const float4*)(src + 4);
            }
            Bs[kq + 0][n] = v0.x; Bs[kq + 1][n] = v0.y;
            Bs[kq + 2][n] = v0.z; Bs[kq + 3][n] = v0.w;
            Bs[kq + 4][n] = v1.x; Bs[kq + 5][n] = v1.y;
            Bs[kq + 6][n] = v1.z; Bs[kq + 7][n] = v1.w;
        }

        __syncthreads();

        #pragma unroll
        for (int kk = 0; kk < 16; kk++) {
            float4 a0 = *(const float4*)&As[kk][ty4];
            float4 a1 = *(const float4*)&As[kk][ty4 + 64];
            float4 b0 = *(const float4*)&Bs[kk][tx4];
            float4 b1 = *(const float4*)&Bs[kk][tx4 + 64];
            float ar[8] = {a0.x, a0.y, a0.z, a0.w, a1.x, a1.y, a1.z, a1.w};
            float br[8] = {b0.x, b0.y, b0.z, b0.w, b1.x, b1.y, b1.z, b1.w};
            #pragma unroll
            for (int i = 0; i < 8; i++)
                #pragma unroll
                for (int j = 0; j < 8; j++)
                    acc[i][j] += ar[i] * br[j];
        }

        __syncthreads();
    }

    #pragma unroll
    for (int ih = 0; ih < 2; ih++) {
        #pragma unroll
        for (int ii = 0; ii < 4; ii++) {
            const int row = m0 + ih * 64 + ty4 + ii;
            #pragma unroll
            for (int jh = 0; jh < 2; jh++) {
                const int col = n0 + jh * 64 + tx4;
                if (NB && col >= N) continue;
                const size_t idx = (size_t)row * N + col;
                float4 v;
                v.x = acc[ih * 4 + ii][jh * 4 + 0];
                v.y = acc[ih * 4 + ii][jh * 4 + 1];
                v.z = acc[ih * 4 + ii][jh * 4 + 2];
                v.w = acc[ih * 4 + ii][jh * 4 + 3];
                if (EPI == 1) {
                    if (row == col + 0) v.x -= 1.0f;
                    if (row == col + 1) v.y -= 1.0f;
                    if (row == col + 2) v.z -= 1.0f;
                    if (row == col + 3) v.w -= 1.0f;
                }
                *(float4*)&C[idx] = v;
            }
        }
    }
}

// convert fp32 G -> fp16 Gh
__global__ void cvt_g_kernel(const float* __restrict__ src, __half* __restrict__ dst)
{
    const size_t i = ((size_t)blockIdx.x * blockDim.x + threadIdx.x) * 4;
    const float4 v = *(const float4*)(src + i);
    const __half h0 = __float2half_rn(v.x), h1 = __float2half_rn(v.y);
    const __half h2 = __float2half_rn(v.z), h3 = __float2half_rn(v.w);
    uint32_t p[2];
    p[0] = ((uint32_t)__half_as_ushort(h1) << 16) | __half_as_ushort(h0);
    p[1] = ((uint32_t)__half_as_ushort(h3) << 16) | __half_as_ushort(h2);
    *(uint2*)(dst + i) = *(const uint2*)p;
}

// u1 = 0.1*b; a1 = thresh(u1) split fp16 hi/lo
__global__ void init_u_kernel(const float* __restrict__ b, float* __restrict__ u,
                              __half* __restrict__ hi, __half* __restrict__ lo)
{
    const size_t i = ((size_t)blockIdx.x * blockDim.x + threadIdx.x) * 4;
    float4 v = *(const float4*)(b + i);
    v.x *= STEPSZ; v.y *= STEPSZ; v.z *= STEPSZ; v.w *= STEPSZ;
    *(float4*)(u + i) = v;
    const float a0 = lca_thresh(v.x), a1 = lca_thresh(v.y);
    const float a2 = lca_thresh(v.z), a3 = lca_thresh(v.w);
    const __half h0 = __float2half_rn(a0), h1 = __float2half_rn(a1);
    const __half h2 = __float2half_rn(a2), h3 = __float2half_rn(a3);
    const __half l0 = __float2half_rn(a0 - __half2float(h0));
    const __half l1 = __float2half_rn(a1 - __half2float(h1));
    const __half l2 = __float2half_rn(a2 - __half2float(h2));
    const __half l3 = __float2half_rn(a3 - __half2float(h3));
    uint32_t hp[2], lp[2];
    hp[0] = ((uint32_t)__half_as_ushort(h1) << 16) | __half_as_ushort(h0);
    hp[1] = ((uint32_t)__half_as_ushort(h3) << 16) | __half_as_ushort(h2);
    lp[0] = ((uint32_t)__half_as_ushort(l1) << 16) | __half_as_ushort(l0);
    lp[1] = ((uint32_t)__half_as_ushort(l3) << 16) | __half_as_ushort(l2);
    *(uint2*)(hi + i) = *(const uint2*)hp;
    *(uint2*)(lo + i) = *(const uint2*)lp;
}

// ============================================================================
extern "C" void kernel_launch(void* const* d_in, const int* in_sizes, int n_in,
                              void* d_out, int out_size) {
    (void)n_in; (void)out_size;

    const float* x = (const float*)d_in[0];
    const float* w = (const float*)d_in[1];
    if (in_sizes[0] == DIM_D * DIM_L) {
        x = (const float*)d_in[1];
        w = (const float*)d_in[0];
    }
    float* out = (float*)d_out;

    float *G, *Bb, *U0, *U1;
    __half *A0h, *A0l, *A1h, *A1l, *Gh;
    cudaGetSymbolAddress((void**)&G,   g_G);
    cudaGetSymbolAddress((void**)&Bb,  g_B);
    cudaGetSymbolAddress((void**)&U0,  g_U0);
    cudaGetSymbolAddress((void**)&U1,  g_U1);
    cudaGetSymbolAddress((void**)&A0h, g_A0h);
    cudaGetSymbolAddress((void**)&A0l, g_A0l);
    cudaGetSymbolAddress((void**)&A1h, g_A1h);
    cudaGetSymbolAddress((void**)&A1l, g_A1l);
    cudaGetSymbolAddress((void**)&Gh,  g_Gh);

    cudaFuncSetAttribute(lca_step_mma,
                         cudaFuncAttributeMaxDynamicSharedMemorySize, STEP_SMEM);

    const dim3 blk(256);

    // g = W^T W - I
    gemm_k<2, 0, 1, false><<<dim3(8, 8), blk>>>(
        w, w, G, DIM_L, DIM_L, DIM_D, DIM_L, DIM_L);

    // b = X W
    gemm_k<0, 0, 0, false><<<dim3(8, 128), blk>>>(
        x, w, Bb, NUM_B, DIM_L, DIM_D, DIM_D, DIM_L);

    // G -> fp16
    cvt_g_kernel<<<(DIM_L * DIM_L) / 4 / 256, 256>>>(G, Gh);

    // step 1: u = 0.1*b, a = thresh(u) split fp16
    init_u_kernel<<<(NUM_B * DIM_L) / 4 / 256, 256>>>(Bb, U0, A0h, A0l);

    // steps 2..49 on tensor pipe (pipelined mma.sync fp16 x2)
    float* uin = U0;  float* uout = U1;
    __half *ahi = A0h, *alo = A0l, *ohi = A1h, *olo = A1l;
    for (int s = 0; s < 48; s++) {
        lca_step_mma<<<dim3(8, 128), 256, STEP_SMEM>>>(
            ahi, alo, Gh, uin, Bb, uout, ohi, olo);
        float* tu = uin; uin = uout; uout = tu;
        __half* t;
        t = ahi; ahi = ohi; ohi = t;
        t = alo; alo = olo; olo = t;
    }

    // recon = thresh(u_final) @ W^T  (fp32 SIMT)
    gemm_k<1, 1, 0, true><<<dim3(7, 128), blk>>>(
        uin, w, out, NUM_B, DIM_D, DIM_L, DIM_L, DIM_L);
}

// round 6
// speedup vs baseline: 4.9715x; 1.7828x over previous
#include <cuda_runtime.h>
#include <cuda_fp16.h>
#include <cstdint>

// Problem constants
#define NUM_B 16384
#define DIM_D 784
#define DIM_L 1024
#define LAMBDA 0.3f
#define STEPSZ 0.1f

// ---------------- scratch (__device__ globals; no allocs allowed) ----------
__device__ float g_G [DIM_L * DIM_L];
__device__ float g_B [(size_t)NUM_B * DIM_L];
__device__ float g_U0[(size_t)NUM_B * DIM_L];
__device__ float g_U1[(size_t)NUM_B * DIM_L];
__device__ __half g_A0[(size_t)NUM_B * DIM_L];    // a = fp16(thresh(u)) ping
__device__ __half g_A1[(size_t)NUM_B * DIM_L];    // a pong
__device__ __half g_Gh[DIM_L * DIM_L];            // fp16(G)

__device__ __forceinline__ float lca_thresh(float x) {
    return x > LAMBDA ? x - LAMBDA : 0.0f;
}

// ---------------- baseline-ISA tensor helpers (sm_80+, valid on sm_103) ----
__device__ __forceinline__ uint32_t smem_u32(const void* p) {
    uint32_t a;
    asm("{ .reg .u64 t; cvta.to.shared.u64 t, %1; cvt.u32.u64 %0, t; }"
        : "=r"(a) : "l"(p));
    return a;
}
__device__ __forceinline__ void cp16(uint32_t dst, const void* src) {
    asm volatile("cp.async.cg.shared.global [%0], [%1], 16;"
                 :: "r"(dst), "l"(src) : "memory");
}
__device__ __forceinline__ void cp_commit() {
    asm volatile("cp.async.commit_group;" ::: "memory");
}
template <int N>
__device__ __forceinline__ void cp_wait() {
    asm volatile("cp.async.wait_group %0;" :: "n"(N) : "memory");
}
__device__ __forceinline__ void ldsm_x4(uint32_t* r, uint32_t a) {
    asm volatile("ldmatrix.sync.aligned.m8n8.x4.shared.b16 {%0,%1,%2,%3}, [%4];"
                 : "=r"(r[0]), "=r"(r[1]), "=r"(r[2]), "=r"(r[3]) : "r"(a));
}
__device__ __forceinline__ void mma_f16(float* c, const uint32_t* a, const uint32_t* b) {
    asm volatile(
        "mma.sync.aligned.m16n8k16.row.col.f32.f16.f16.f32 "
        "{%0,%1,%2,%3}, {%4,%5,%6,%7}, {%8,%9}, {%0,%1,%2,%3};"
        : "+f"(c[0]), "+f"(c[1]), "+f"(c[2]), "+f"(c[3])
        : "r"(a[0]), "r"(a[1]), "r"(a[2]), "r"(a[3]), "r"(b[0]), "r"(b[1]));
}

// ============================================================================
// Single-product LCA step:  D = a@G_h (fp16),  u' = 0.9u + 0.1b - 0.1D,
// fused write of u' (fp32) and a' = fp16(thresh(u')).
// Grid (8,128), 256 threads. BK=64, 2-stage cp.async pipeline, 72KB smem.
// ============================================================================
#define BK   64
#define PAD  72                        // fp16/row (144B pitch, ldmatrix conflict-free)
#define TILE_B    (128 * PAD * 2)      // 18432 B per tile
#define STAGE_B   (2 * TILE_B)         // 36864 B per stage (A, G)
#define STEP_SMEM (2 * STAGE_B)        // 73728 B
#define NC   (DIM_L / BK)              // 16 chunks

__global__ __launch_bounds__(256, 2)
void lca_step_mma(const __half* __restrict__ Ain,
                  const __half* __restrict__ Gh,
                  const float* __restrict__ Uin,
                  const float* __restrict__ Bex,
                  float* __restrict__ Uout,
                  __half* __restrict__ Aout)
{
    extern __shared__ __align__(16) char dsmem[];
    const uint32_t sb = smem_u32(dsmem);

    const int tid  = threadIdx.x;
    const int lane = tid & 31;
    const int wid  = tid >> 5;
    const int wy   = wid >> 2;   // 0..1 (M)
    const int wx   = wid & 3;    // 0..3 (N)
    const int m0   = blockIdx.y * 128;
    const int n0   = blockIdx.x * 128;

    // A ldmatrix (x4, row-major 16x16): lanes 0-15 rows, lanes 16-31 k-half 1
    const int a_row = lane & 15;
    const int a_kh  = lane >> 4;
    uint32_t aoffs[4];
    #pragma unroll
    for (int mi = 0; mi < 4; mi++)
        aoffs[mi] = (uint32_t)((wy * 64 + mi * 16 + a_row) * PAD + a_kh * 8) * 2;

    // B ldmatrix (x4 covering ni pair): m0=(n:+0..7,k:0-7) m1=(same n,k:8-15)
    //                                   m2=(n:+8..15,k:0-7) m3=(same,k:8-15)
    const int b_nr = ((lane >> 4) & 1) * 8 + (lane & 7);
    const int b_kh = (lane >> 3) & 1;
    uint32_t boffs[2];
    #pragma unroll
    for (int p = 0; p < 2; p++)
        boffs[p] = (uint32_t)((wx * 32 + p * 16 + b_nr) * PAD + b_kh * 8) * 2;

    // cp.async mapping: per tile 128 rows x 128B; 4 chunks of 16B per thread
    const int c_row = tid >> 3;          // 0..31 (+t*32)
    const int c_col = (tid & 7) * 8;     // fp16 col

    float acc[4][4][4];
    #pragma unroll
    for (int i = 0; i < 4; i++)
        #pragma unroll
        for (int j = 0; j < 4; j++)
            #pragma unroll
            for (int q = 0; q < 4; q++) acc[i][j][q] = 0.0f;

    auto issue = [&](int c, int stage) {
        const int k0 = c * BK;
        const uint32_t base = sb + stage * STAGE_B;
        #pragma unroll
        for (int t = 0; t < 4; t++) {
            const int row = c_row + t * 32;
            const uint32_t soff = (uint32_t)(row * PAD + c_col) * 2;
            cp16(base + soff,          Ain + (size_t)(m0 + row) * DIM_L + k0 + c_col);
            cp16(base + TILE_B + soff, Gh  + (size_t)(n0 + row) * DIM_L + k0 + c_col);
        }
        cp_commit();
    };

    issue(0, 0);

    #pragma unroll 1
    for (int c = 0; c < NC; c++) {
        if (c + 1 < NC) {
            issue(c + 1, (c + 1) & 1);
            cp_wait<1>();
        } else {
            cp_wait<0>();
        }
        __syncthreads();

        const uint32_t base = sb + (c & 1) * STAGE_B;
        const uint32_t uA = base;
        const uint32_t uG = base + TILE_B;

        #pragma unroll
        for (int kk = 0; kk < BK; kk += 16) {
            const uint32_t kb = (uint32_t)kk * 2;
            uint32_t af[4][4];
            uint32_t bq[2][4];
            #pragma unroll
            for (int p = 0; p < 2; p++)
                ldsm_x4(bq[p], uG + boffs[p] + kb);
            #pragma unroll
            for (int mi = 0; mi < 4; mi++)
                ldsm_x4(af[mi], uA + aoffs[mi] + kb);
            #pragma unroll
            for (int mi = 0; mi < 4; mi++)
                #pragma unroll
                for (int ni = 0; ni < 4; ni++)
                    mma_f16(acc[mi][ni], af[mi], &bq[ni >> 1][(ni & 1) * 2]);
        }
        __syncthreads();
    }

    // ---------------- fused epilogue ----------------
    const int g  = lane >> 2;
    const int tg = lane & 3;
    #pragma unroll
    for (int mi = 0; mi < 4; mi++) {
        #pragma unroll
        for (int ni = 0; ni < 4; ni++) {
            const int r0 = m0 + wy * 64 + mi * 16 + g;
            const int c0 = n0 + wx * 32 + ni * 8 + tg * 2;
            #pragma unroll
            for (int h = 0; h < 2; h++) {
                const size_t idx = (size_t)(r0 + h * 8) * DIM_L + c0;
                const float d0 = acc[mi][ni][h * 2 + 0];
                const float d1 = acc[mi][ni][h * 2 + 1];
                const float2 u2 = *(const float2*)(Uin + idx);
                const float2 b2 = *(const float2*)(Bex + idx);
                float vx = (1.0f - STEPSZ) * u2.x + STEPSZ * b2.x - STEPSZ * d0;
                float vy = (1.0f - STEPSZ) * u2.y + STEPSZ * b2.y - STEPSZ * d1;
                *(float2*)(Uout + idx) = make_float2(vx, vy);
                const __half h0 = __float2half_rn(lca_thresh(vx));
                const __half h1 = __float2half_rn(lca_thresh(vy));
                *(uint32_t*)(Aout + idx) =
                    ((uint32_t)__half_as_ushort(h1) << 16) | __half_as_ushort(h0);
            }
        }
    }
}

// ============================================================================
// SIMT fp32 GEMM (R1) for g, b, recon
// ============================================================================
template<int OPA, int OPB, int EPI, bool NB>
__global__ __launch_bounds__(256, 2)
void gemm_k(const float* __restrict__ A, const float* __restrict__ Bm,
            float* __restrict__ C,
            int M, int N, int K, int lda, int ldb)
{
    __shared__ float As[16][128];
    __shared__ float Bs[16][128];

    const int tid = threadIdx.x;
    const int m0 = blockIdx.y * 128;
    const int n0 = blockIdx.x * 128;
    const int tx4 = (tid & 15) * 4;
    const int ty4 = (tid >> 4) * 4;

    float acc[8][8];
    #pragma unroll
    for (int i = 0; i < 8; i++)
        #pragma unroll
        for (int j = 0; j < 8; j++) acc[i][j] = 0.0f;

    for (int k0 = 0; k0 < K; k0 += 16) {
        if (OPA == 0 || OPA == 1) {
            const int m  = tid & 127;
            const int kq = (tid >> 7) * 8;
            const float* src = A + (size_t)(m0 + m) * lda + k0 + kq;
            float4 v0 = *(const float4*)(src);
            float4 v1 = *(const float4*)(src + 4);
            if (OPA == 1) {
                v0.x = lca_thresh(v0.x); v0.y = lca_thresh(v0.y);
                v0.z = lca_thresh(v0.z); v0.w = lca_thresh(v0.w);
                v1.x = lca_thresh(v1.x); v1.y = lca_thresh(v1.y);
                v1.z = lca_thresh(v1.z); v1.w = lca_thresh(v1.w);
            }
            As[kq + 0][m] = v0.x; As[kq + 1][m] = v0.y;
            As[kq + 2][m] = v0.z; As[kq + 3][m] = v0.w;
            As[kq + 4][m] = v1.x; As[kq + 5][m] = v1.y;
            As[kq + 6][m] = v1.z; As[kq + 7][m] = v1.w;
        } else {
            const int k  = tid >> 4;
            const int mq = (tid & 15) * 8;
            const float* src = A + (size_t)(k0 + k) * lda + m0 + mq;
            *(float4*)&As[k][mq]     = *(const float4*)(src);
            *(float4*)&As[k][mq + 4] = *(const float4*)(src + 4);
        }

        if (OPB == 0) {
            const int k  = tid >> 4;
            const int nq = (tid & 15) * 8;
            const float* src = Bm + (size_t)(k0 + k) * ldb + n0 + nq;
            *(float4*)&Bs[k][nq]     = *(const float4*)(src);
            *(float4*)&Bs[k][nq + 4] = *(const float4*)(src + 4);
        } else {
            const int n  = tid & 127;
            const int kq = (tid >> 7) * 8;
            float4 v0 = make_float4(0.f, 0.f, 0.f, 0.f);
            float4 v1 = v0;
            if (!NB || (n0 + n) < N) {
                const float* src = Bm + (size_t)(n0 + n) * ldb + k0 + kq;
                v0 = *(const float4*)(src);
                v1 = *(const float4*)(src + 4);
            }
            Bs[kq + 0][n] = v0.x; Bs[kq + 1][n] = v0.y;
            Bs[kq + 2][n] = v0.z; Bs[kq + 3][n] = v0.w;
            Bs[kq + 4][n] = v1.x; Bs[kq + 5][n] = v1.y;
            Bs[kq + 6][n] = v1.z; Bs[kq + 7][n] = v1.w;
        }

        __syncthreads();

        #pragma unroll
        for (int kk = 0; kk < 16; kk++) {
            float4 a0 = *(const float4*)&As[kk][ty4];
            float4 a1 = *(const float4*)&As[kk][ty4 + 64];
            float4 b0 = *(const float4*)&Bs[kk][tx4];
            float4 b1 = *(const float4*)&Bs[kk][tx4 + 64];
            float ar[8] = {a0.x, a0.y, a0.z, a0.w, a1.x, a1.y, a1.z, a1.w};
            float br[8] = {b0.x, b0.y, b0.z, b0.w, b1.x, b1.y, b1.z, b1.w};
            #pragma unroll
            for (int i = 0; i < 8; i++)
                #pragma unroll
                for (int j = 0; j < 8; j++)
                    acc[i][j] += ar[i] * br[j];
        }

        __syncthreads();
    }

    #pragma unroll
    for (int ih = 0; ih < 2; ih++) {
        #pragma unroll
        for (int ii = 0; ii < 4; ii++) {
            const int row = m0 + ih * 64 + ty4 + ii;
            #pragma unroll
            for (int jh = 0; jh < 2; jh++) {
                const int col = n0 + jh * 64 + tx4;
                if (NB && col >= N) continue;
                const size_t idx = (size_t)row * N + col;
                float4 v;
                v.x = acc[ih * 4 + ii][jh * 4 + 0];
                v.y = acc[ih * 4 + ii][jh * 4 + 1];
                v.z = acc[ih * 4 + ii][jh * 4 + 2];
                v.w = acc[ih * 4 + ii][jh * 4 + 3];
                if (EPI == 1) {
                    if (row == col + 0) v.x -= 1.0f;
                    if (row == col + 1) v.y -= 1.0f;
                    if (row == col + 2) v.z -= 1.0f;
                    if (row == col + 3) v.w -= 1.0f;
                }
                *(float4*)&C[idx] = v;
            }
        }
    }
}

// convert fp32 G -> fp16 Gh
__global__ void cvt_g_kernel(const float* __restrict__ src, __half* __restrict__ dst)
{
    const size_t i = ((size_t)blockIdx.x * blockDim.x + threadIdx.x) * 4;
    const float4 v = *(const float4*)(src + i);
    const __half h0 = __float2half_rn(v.x), h1 = __float2half_rn(v.y);
    const __half h2 = __float2half_rn(v.z), h3 = __float2half_rn(v.w);
    uint32_t p[2];
    p[0] = ((uint32_t)__half_as_ushort(h1) << 16) | __half_as_ushort(h0);
    p[1] = ((uint32_t)__half_as_ushort(h3) << 16) | __half_as_ushort(h2);
    *(uint2*)(dst + i) = *(const uint2*)p;
}

// u1 = 0.1*b; a1 = fp16(thresh(u1))
__global__ void init_u_kernel(const float* __restrict__ b, float* __restrict__ u,
                              __half* __restrict__ a)
{
    const size_t i = ((size_t)blockIdx.x * blockDim.x + threadIdx.x) * 4;
    float4 v = *(const float4*)(b + i);
    v.x *= STEPSZ; v.y *= STEPSZ; v.z *= STEPSZ; v.w *= STEPSZ;
    *(float4*)(u + i) = v;
    const __half h0 = __float2half_rn(lca_thresh(v.x));
    const __half h1 = __float2half_rn(lca_thresh(v.y));
    const __half h2 = __float2half_rn(lca_thresh(v.z));
    const __half h3 = __float2half_rn(lca_thresh(v.w));
    uint32_t p[2];
    p[0] = ((uint32_t)__half_as_ushort(h1) << 16) | __half_as_ushort(h0);
    p[1] = ((uint32_t)__half_as_ushort(h3) << 16) | __half_as_ushort(h2);
    *(uint2*)(a + i) = *(const uint2*)p;
}

// ============================================================================
extern "C" void kernel_launch(void* const* d_in, const int* in_sizes, int n_in,
                              void* d_out, int out_size) {
    (void)n_in; (void)out_size;

    const float* x = (const float*)d_in[0];
    const float* w = (const float*)d_in[1];
    if (in_sizes[0] == DIM_D * DIM_L) {
        x = (const float*)d_in[1];
        w = (const float*)d_in[0];
    }
    float* out = (float*)d_out;

    float *G, *Bb, *U0, *U1;
    __half *A0, *A1, *Gh;
    cudaGetSymbolAddress((void**)&G,  g_G);
    cudaGetSymbolAddress((void**)&Bb, g_B);
    cudaGetSymbolAddress((void**)&U0, g_U0);
    cudaGetSymbolAddress((void**)&U1, g_U1);
    cudaGetSymbolAddress((void**)&A0, g_A0);
    cudaGetSymbolAddress((void**)&A1, g_A1);
    cudaGetSymbolAddress((void**)&Gh, g_Gh);

    cudaFuncSetAttribute(lca_step_mma,
                         cudaFuncAttributeMaxDynamicSharedMemorySize, STEP_SMEM);

    const dim3 blk(256);

    // g = W^T W - I
    gemm_k<2, 0, 1, false><<<dim3(8, 8), blk>>>(
        w, w, G, DIM_L, DIM_L, DIM_D, DIM_L, DIM_L);

    // b = X W
    gemm_k<0, 0, 0, false><<<dim3(8, 128), blk>>>(
        x, w, Bb, NUM_B, DIM_L, DIM_D, DIM_D, DIM_L);

    // G -> fp16
    cvt_g_kernel<<<(DIM_L * DIM_L) / 4 / 256, 256>>>(G, Gh);

    // step 1: u = 0.1*b, a = fp16(thresh(u))
    init_u_kernel<<<(NUM_B * DIM_L) / 4 / 256, 256>>>(Bb, U0, A0);

    // steps 2..49 on tensor pipe (single-product fp16 mma.sync)
    float* uin = U0;  float* uout = U1;
    __half *ain = A0, *aout = A1;
    for (int s = 0; s < 48; s++) {
        lca_step_mma<<<dim3(8, 128), 256, STEP_SMEM>>>(
            ain, Gh, uin, Bb, uout, aout);
        float* tu = uin; uin = uout; uout = tu;
        __half* ta = ain; ain = aout; aout = ta;
    }

    // recon = thresh(u_final) @ W^T  (fp32 SIMT)
    gemm_k<1, 1, 0, true><<<dim3(7, 128), blk>>>(
        uin, w, out, NUM_B, DIM_D, DIM_L, DIM_L, DIM_L);
}

// round 7
// speedup vs baseline: 5.5087x; 1.1081x over previous
#include <cuda_runtime.h>
#include <cuda_fp16.h>
#include <cstdint>

// Problem constants
#define NUM_B 16384
#define DIM_D 784
#define DIM_L 1024
#define KXP   832          // K of X padded to multiple of 64
#define NRP   896          // recon N padded to multiple of 128
#define LAMBDA 0.3f
#define STEPSZ 0.1f

// ---------------- scratch (__device__ globals; no allocs allowed) ----------
__device__ float g_G [DIM_L * DIM_L];                 // fp32 g = W^T W - I
__device__ float g_B [(size_t)NUM_B * DIM_L];         // fp32 b
__device__ float g_U0[(size_t)NUM_B * DIM_L];
__device__ float g_U1[(size_t)NUM_B * DIM_L];
__device__ __half g_Aa[(size_t)NUM_B * DIM_L];        // a ping (fp16)
__device__ __half g_Ab[(size_t)NUM_B * DIM_L];        // a pong
__device__ __half g_Ac[(size_t)NUM_B * DIM_L];        // a_lo for recon
__device__ __half g_Gh[DIM_L * DIM_L];                // fp16(G)
__device__ __half g_XPh[(size_t)NUM_B * KXP];         // X hi, K-padded
__device__ __half g_XPl[(size_t)NUM_B * KXP];         // X lo
__device__ __half g_WT [DIM_L * KXP];                 // W^T fp16 [L, KXP]
__device__ __half g_WR [NRP * DIM_L];                 // W fp16 padded [NRP, L]

__device__ __forceinline__ float lca_thresh(float x) {
    return x > LAMBDA ? x - LAMBDA : 0.0f;
}

// ---------------- baseline-ISA tensor helpers ----------
__device__ __forceinline__ uint32_t smem_u32(const void* p) {
    uint32_t a;
    asm("{ .reg .u64 t; cvta.to.shared.u64 t, %1; cvt.u32.u64 %0, t; }"
        : "=r"(a) : "l"(p));
    return a;
}
__device__ __forceinline__ void cp16(uint32_t dst, const void* src) {
    asm volatile("cp.async.cg.shared.global [%0], [%1], 16;"
                 :: "r"(dst), "l"(src) : "memory");
}
__device__ __forceinline__ void cp_commit() {
    asm volatile("cp.async.commit_group;" ::: "memory");
}
template <int N>
__device__ __forceinline__ void cp_wait() {
    asm volatile("cp.async.wait_group %0;" :: "n"(N) : "memory");
}
__device__ __forceinline__ void ldsm_x4(uint32_t* r, uint32_t a) {
    asm volatile("ldmatrix.sync.aligned.m8n8.x4.shared.b16 {%0,%1,%2,%3}, [%4];"
                 : "=r"(r[0]), "=r"(r[1]), "=r"(r[2]), "=r"(r[3]) : "r"(a));
}
__device__ __forceinline__ void mma_f16(float* c, const uint32_t* a, const uint32_t* b) {
    asm volatile(
        "mma.sync.aligned.m16n8k16.row.col.f32.f16.f16.f32 "
        "{%0,%1,%2,%3}, {%4,%5,%6,%7}, {%8,%9}, {%0,%1,%2,%3};"
        : "+f"(c[0]), "+f"(c[1]), "+f"(c[2]), "+f"(c[3])
        : "r"(a[0]), "r"(a[1]), "r"(a[2]), "r"(a[3]), "r"(b[0]), "r"(b[1]));
}

// ============================================================================
// Generic fp16 mma GEMM, 128x128 tile, BK=64, 2-stage cp.async pipeline.
// D = A0@B (+ A1@B if NPROD==2), fp32 accum. Epilogues:
//  EPI 0: step     u' = 0.9u + 0.1b - 0.1D; write Uout fp32, Aout=fp16(thresh)
//  EPI 1: step-last same, but write Aout=hi, Aout2=lo fp16 split of thresh(u')
//  EPI 2: b        write Cout=D fp32, Uout=0.1D, Aout=fp16(thresh(0.1D))
//  EPI 3: recon    write Cout=D fp32 with col<DIM_D guard, ld=DIM_D
// ============================================================================
#define BK   64
#define PAD  72                        // fp16/row (144B pitch, conflict-free)
#define TILE_B (128 * PAD * 2)         // 18432 B

template<int NPROD, int EPI>
__global__ __launch_bounds__(256, 2)
void mma_gemm(const __half* __restrict__ A0p, const __half* __restrict__ A1p,
              const __half* __restrict__ Bmp,
              const float* __restrict__ Uin, const float* __restrict__ Bex,
              float* __restrict__ Uout,
              __half* __restrict__ Aout, __half* __restrict__ Aout2,
              float* __restrict__ Cout,
              int Kdim, int ldA, int ldB)
{
    constexpr int STAGE_B = (NPROD + 1) * TILE_B;
    extern __shared__ __align__(16) char dsmem[];
    const uint32_t sb = smem_u32(dsmem);

    const int tid  = threadIdx.x;
    const int lane = tid & 31;
    const int wid  = tid >> 5;
    const int wy   = wid >> 2;   // 0..1 (M)
    const int wx   = wid & 3;    // 0..3 (N)
    const int m0   = blockIdx.y * 128;
    const int n0   = blockIdx.x * 128;
    const int NC   = Kdim >> 6;

    // A ldmatrix (x4 row-major 16x16)
    const int a_row = lane & 15;
    const int a_kh  = lane >> 4;
    uint32_t aoffs[4];
    #pragma unroll
    for (int mi = 0; mi < 4; mi++)
        aoffs[mi] = (uint32_t)((wy * 64 + mi * 16 + a_row) * PAD + a_kh * 8) * 2;

    // B ldmatrix (x4 covering an ni pair)
    const int b_nr = ((lane >> 4) & 1) * 8 + (lane & 7);
    const int b_kh = (lane >> 3) & 1;
    uint32_t boffs[2];
    #pragma unroll
    for (int p = 0; p < 2; p++)
        boffs[p] = (uint32_t)((wx * 32 + p * 16 + b_nr) * PAD + b_kh * 8) * 2;

    // cp.async mapping: per tile 128 rows x 64 fp16; 4x16B per thread
    const int c_row = tid >> 3;
    const int c_col = (tid & 7) * 8;

    float acc[4][4][4];
    #pragma unroll
    for (int i = 0; i < 4; i++)
        #pragma unroll
        for (int j = 0; j < 4; j++)
            #pragma unroll
            for (int q = 0; q < 4; q++) acc[i][j][q] = 0.0f;

    auto issue = [&](int c, int stage) {
        const int k0 = c * BK;
        const uint32_t base = sb + stage * STAGE_B;
        #pragma unroll
        for (int t = 0; t < 4; t++) {
            const int row = c_row + t * 32;
            const uint32_t soff = (uint32_t)(row * PAD + c_col) * 2;
            cp16(base + soff, A0p + (size_t)(m0 + row) * ldA + k0 + c_col);
            if (NPROD == 2)
                cp16(base + TILE_B + soff, A1p + (size_t)(m0 + row) * ldA + k0 + c_col);
            cp16(base + NPROD * TILE_B + soff, Bmp + (size_t)(n0 + row) * ldB + k0 + c_col);
        }
        cp_commit();
    };

    issue(0, 0);

    #pragma unroll 1
    for (int c = 0; c < NC; c++) {
        if (c + 1 < NC) {
            issue(c + 1, (c + 1) & 1);
            cp_wait<1>();
        } else {
            cp_wait<0>();
        }
        __syncthreads();

        const uint32_t base = sb + (c & 1) * STAGE_B;
        const uint32_t uG = base + NPROD * TILE_B;

        #pragma unroll
        for (int kk = 0; kk < BK; kk += 16) {
            const uint32_t kb = (uint32_t)kk * 2;
            uint32_t af[4][4];
            uint32_t bq[2][4];
            #pragma unroll
            for (int p = 0; p < 2; p++)
                ldsm_x4(bq[p], uG + boffs[p] + kb);
            #pragma unroll
            for (int mi = 0; mi < 4; mi++)
                ldsm_x4(af[mi], base + aoffs[mi] + kb);
            #pragma unroll
            for (int mi = 0; mi < 4; mi++)
                #pragma unroll
                for (int ni = 0; ni < 4; ni++)
                    mma_f16(acc[mi][ni], af[mi], &bq[ni >> 1][(ni & 1) * 2]);
            if (NPROD == 2) {
                #pragma unroll
                for (int mi = 0; mi < 4; mi++)
                    ldsm_x4(af[mi], base + TILE_B + aoffs[mi] + kb);
                #pragma unroll
                for (int mi = 0; mi < 4; mi++)
                    #pragma unroll
                    for (int ni = 0; ni < 4; ni++)
                        mma_f16(acc[mi][ni], af[mi], &bq[ni >> 1][(ni & 1) * 2]);
            }
        }
        __syncthreads();
    }

    // ---------------- epilogue ----------------
    const int g  = lane >> 2;
    const int tg = lane & 3;
    #pragma unroll
    for (int mi = 0; mi < 4; mi++) {
        #pragma unroll
        for (int ni = 0; ni < 4; ni++) {
            #pragma unroll
            for (int h = 0; h < 2; h++) {
                const int r = m0 + wy * 64 + mi * 16 + g + h * 8;
                const int c0 = n0 + wx * 32 + ni * 8 + tg * 2;
                const float d0 = acc[mi][ni][h * 2 + 0];
                const float d1 = acc[mi][ni][h * 2 + 1];
                if (EPI == 0 || EPI == 1) {
                    const size_t idx = (size_t)r * DIM_L + c0;
                    const float2 u2 = *(const float2*)(Uin + idx);
                    const float2 b2 = *(const float2*)(Bex + idx);
                    const float vx = (1.0f - STEPSZ) * u2.x + STEPSZ * b2.x - STEPSZ * d0;
                    const float vy = (1.0f - STEPSZ) * u2.y + STEPSZ * b2.y - STEPSZ * d1;
                    *(float2*)(Uout + idx) = make_float2(vx, vy);
                    const float a0 = lca_thresh(vx), a1 = lca_thresh(vy);
                    const __half h0 = __float2half_rn(a0);
                    const __half h1 = __float2half_rn(a1);
                    *(uint32_t*)(Aout + idx) =
                        ((uint32_t)__half_as_ushort(h1) << 16) | __half_as_ushort(h0);
                    if (EPI == 1) {
                        const __half l0 = __float2half_rn(a0 - __half2float(h0));
                        const __half l1 = __float2half_rn(a1 - __half2float(h1));
                        *(uint32_t*)(Aout2 + idx) =
                            ((uint32_t)__half_as_ushort(l1) << 16) | __half_as_ushort(l0);
                    }
                } else if (EPI == 2) {
                    const size_t idx = (size_t)r * DIM_L + c0;
                    *(float2*)(Cout + idx) = make_float2(d0, d1);
                    const float vx = STEPSZ * d0, vy = STEPSZ * d1;
                    *(float2*)(Uout + idx) = make_float2(vx, vy);
                    const __half h0 = __float2half_rn(lca_thresh(vx));
                    const __half h1 = __float2half_rn(lca_thresh(vy));
                    *(uint32_t*)(Aout + idx) =
                        ((uint32_t)__half_as_ushort(h1) << 16) | __half_as_ushort(h0);
                } else { // EPI == 3 (recon)
                    if (c0 < DIM_D)
                        *(float2*)(Cout + (size_t)r * DIM_D + c0) = make_float2(d0, d1);
                }
            }
        }
    }
}

// ============================================================================
// SIMT fp32 GEMM — used only for g = W^T W - I (small)
// ============================================================================
__global__ __launch_bounds__(256, 2)
void gemm_g(const float* __restrict__ W, float* __restrict__ C)
{
    __shared__ float As[16][128];
    __shared__ float Bs[16][128];

    const int tid = threadIdx.x;
    const int m0 = blockIdx.y * 128;
    const int n0 = blockIdx.x * 128;
    const int tx4 = (tid & 15) * 4;
    const int ty4 = (tid >> 4) * 4;

    float acc[8][8];
    #pragma unroll
    for (int i = 0; i < 8; i++)
        #pragma unroll
        for (int j = 0; j < 8; j++) acc[i][j] = 0.0f;

    for (int k0 = 0; k0 < DIM_D; k0 += 16) {
        {   // A[m,k] = W[k*L + m]
            const int k  = tid >> 4;
            const int mq = (tid & 15) * 8;
            const float* src = W + (size_t)(k0 + k) * DIM_L + m0 + mq;
            *(float4*)&As[k][mq]     = *(const float4*)(src);
            *(float4*)&As[k][mq + 4] = *(const float4*)(src + 4);
        }
        {   // B[k,n] = W[k*L + n]
            const int k  = tid >> 4;
            const int nq = (tid & 15) * 8;
            const float* src = W + (size_t)(k0 + k) * DIM_L + n0 + nq;
            *(float4*)&Bs[k][nq]     = *(const float4*)(src);
            *(float4*)&Bs[k][nq + 4] = *(const float4*)(src + 4);
        }
        __syncthreads();
        #pragma unroll
        for (int kk = 0; kk < 16; kk++) {
            float4 a0 = *(const float4*)&As[kk][ty4];
            float4 a1 = *(const float4*)&As[kk][ty4 + 64];
            float4 b0 = *(const float4*)&Bs[kk][tx4];
            float4 b1 = *(const float4*)&Bs[kk][tx4 + 64];
            float ar[8] = {a0.x, a0.y, a0.z, a0.w, a1.x, a1.y, a1.z, a1.w};
            float br[8] = {b0.x, b0.y, b0.z, b0.w, b1.x, b1.y, b1.z, b1.w};
            #pragma unroll
            for (int i = 0; i < 8; i++)
                #pragma unroll
                for (int j = 0; j < 8; j++)
                    acc[i][j] += ar[i] * br[j];
        }
        __syncthreads();
    }

    #pragma unroll
    for (int ih = 0; ih < 2; ih++)
        #pragma unroll
        for (int ii = 0; ii < 4; ii++) {
            const int row = m0 + ih * 64 + ty4 + ii;
            #pragma unroll
            for (int jh = 0; jh < 2; jh++) {
                const int col = n0 + jh * 64 + tx4;
                const size_t idx = (size_t)row * DIM_L + col;
                float4 v;
                v.x = acc[ih * 4 + ii][jh * 4 + 0];
                v.y = acc[ih * 4 + ii][jh * 4 + 1];
                v.z = acc[ih * 4 + ii][jh * 4 + 2];
                v.w = acc[ih * 4 + ii][jh * 4 + 3];
                if (row == col + 0) v.x -= 1.0f;
                if (row == col + 1) v.y -= 1.0f;
                if (row == col + 2) v.z -= 1.0f;
                if (row == col + 3) v.w -= 1.0f;
                *(float4*)&C[idx] = v;
            }
        }
}

// ---------------- conversion kernels (one-time) ----------------
__global__ void cvt_g_kernel(const float* __restrict__ src, __half* __restrict__ dst)
{
    const size_t i = ((size_t)blockIdx.x * blockDim.x + threadIdx.x) * 4;
    const float4 v = *(const float4*)(src + i);
    uint32_t p[2];
    p[0] = ((uint32_t)__half_as_ushort(__float2half_rn(v.y)) << 16) |
           __half_as_ushort(__float2half_rn(v.x));
    p[1] = ((uint32_t)__half_as_ushort(__float2half_rn(v.w)) << 16) |
           __half_as_ushort(__float2half_rn(v.z));
    *(uint2*)(dst + i) = *(const uint2*)p;
}

// X [NUM_B,784] -> XPh/XPl [NUM_B,832] fp16 hi/lo, zero pad
__global__ void split_pad_x(const float* __restrict__ X,
                            __half* __restrict__ hi, __half* __restrict__ lo)
{
    const size_t v = (size_t)blockIdx.x * blockDim.x + threadIdx.x;
    const int row = (int)(v / (KXP / 4));
    const int c4  = (int)(v % (KXP / 4)) * 4;
    uint32_t hp[2] = {0, 0}, lp[2] = {0, 0};
    if (c4 < DIM_D) {
        const float4 x = *(const float4*)(X + (size_t)row * DIM_D + c4);
        const __half h0 = __float2half_rn(x.x), h1 = __float2half_rn(x.y);
        const __half h2 = __float2half_rn(x.z), h3 = __float2half_rn(x.w);
        const __half l0 = __float2half_rn(x.x - __half2float(h0));
        const __half l1 = __float2half_rn(x.y - __half2float(h1));
        const __half l2 = __float2half_rn(x.z - __half2float(h2));
        const __half l3 = __float2half_rn(x.w - __half2float(h3));
        hp[0] = ((uint32_t)__half_as_ushort(h1) << 16) | __half_as_ushort(h0);
        hp[1] = ((uint32_t)__half_as_ushort(h3) << 16) | __half_as_ushort(h2);
        lp[0] = ((uint32_t)__half_as_ushort(l1) << 16) | __half_as_ushort(l0);
        lp[1] = ((uint32_t)__half_as_ushort(l3) << 16) | __half_as_ushort(l2);
    }
    const size_t o = (size_t)row * KXP + c4;
    *(uint2*)(hi + o) = *(const uint2*)hp;
    *(uint2*)(lo + o) = *(const uint2*)lp;
}

// WT [L, KXP] fp16 : WT[n,k] = W[k,n] (k<784), else 0
__global__ void transpose_w(const float* __restrict__ W, __half* __restrict__ WT)
{
    const size_t i = (size_t)blockIdx.x * blockDim.x + threadIdx.x;
    if (i >= (size_t)DIM_L * KXP) return;
    const int n = (int)(i / KXP);
    const int k = (int)(i % KXP);
    const float v = (k < DIM_D) ? W[(size_t)k * DIM_L + n] : 0.0f;
    WT[i] = __float2half_rn(v);
}

// WR [NRP, L] fp16 : rows < 784 = fp16(W), else 0
__global__ void pad_w(const float* __restrict__ W, __half* __restrict__ WR)
{
    const size_t i = ((size_t)blockIdx.x * blockDim.x + threadIdx.x) * 4;
    if (i >= (size_t)NRP * DIM_L) return;
    const int row = (int)(i / DIM_L);
    uint32_t p[2] = {0, 0};
    if (row < DIM_D) {
        const float4 v = *(const float4*)(W + i);
        p[0] = ((uint32_t)__half_as_ushort(__float2half_rn(v.y)) << 16) |
               __half_as_ushort(__float2half_rn(v.x));
        p[1] = ((uint32_t)__half_as_ushort(__float2half_rn(v.w)) << 16) |
               __half_as_ushort(__float2half_rn(v.z));
    }
    *(uint2*)(WR + i) = *(const uint2*)p;
}

// ============================================================================
extern "C" void kernel_launch(void* const* d_in, const int* in_sizes, int n_in,
                              void* d_out, int out_size) {
    (void)n_in; (void)out_size;

    const float* x = (const float*)d_in[0];
    const float* w = (const float*)d_in[1];
    if (in_sizes[0] == DIM_D * DIM_L) {
        x = (const float*)d_in[1];
        w = (const float*)d_in[0];
    }
    float* out = (float*)d_out;

    float *G, *Bb, *U0, *U1;
    __half *Aa, *Ab, *Ac, *Gh, *XPh, *XPl, *WT, *WR;
    cudaGetSymbolAddress((void**)&G,   g_G);
    cudaGetSymbolAddress((void**)&Bb,  g_B);
    cudaGetSymbolAddress((void**)&U0,  g_U0);
    cudaGetSymbolAddress((void**)&U1,  g_U1);
    cudaGetSymbolAddress((void**)&Aa,  g_Aa);
    cudaGetSymbolAddress((void**)&Ab,  g_Ab);
    cudaGetSymbolAddress((void**)&Ac,  g_Ac);
    cudaGetSymbolAddress((void**)&Gh,  g_Gh);
    cudaGetSymbolAddress((void**)&XPh, g_XPh);
    cudaGetSymbolAddress((void**)&XPl, g_XPl);
    cudaGetSymbolAddress((void**)&WT,  g_WT);
    cudaGetSymbolAddress((void**)&WR,  g_WR);

    const int SM1 = 2 * 2 * TILE_B;   // NPROD=1: 73728
    const int SM2 = 2 * 3 * TILE_B;   // NPROD=2: 110592
    cudaFuncSetAttribute(mma_gemm<1, 0>, cudaFuncAttributeMaxDynamicSharedMemorySize, SM1);
    cudaFuncSetAttribute(mma_gemm<1, 1>, cudaFuncAttributeMaxDynamicSharedMemorySize, SM1);
    cudaFuncSetAttribute(mma_gemm<2, 2>, cudaFuncAttributeMaxDynamicSharedMemorySize, SM2);
    cudaFuncSetAttribute(mma_gemm<2, 3>, cudaFuncAttributeMaxDynamicSharedMemorySize, SM2);

    // g = W^T W - I  (fp32 SIMT, small)
    gemm_g<<<dim3(8, 8), 256>>>(w, G);
    // conversions
    cvt_g_kernel<<<(DIM_L * DIM_L) / 4 / 256, 256>>>(G, Gh);
    split_pad_x<<<(int)(((size_t)NUM_B * KXP / 4) / 256), 256>>>(x, XPh, XPl);
    transpose_w<<<(DIM_L * KXP + 255) / 256, 256>>>(w, WT);
    pad_w<<<(NRP * DIM_L / 4 + 255) / 256, 256>>>(w, WR);

    // b = X@W (fp16 2-product) + fused u1 = 0.1b, a1 = fp16(thresh(u1))
    mma_gemm<2, 2><<<dim3(8, 128), 256, SM2>>>(
        XPh, XPl, WT, nullptr, nullptr, U0, Aa, nullptr, Bb, KXP, KXP, KXP);

    // steps 2..49: 47 normal + 1 split-output
    float* uin = U0;  float* uout = U1;
    __half *ain = Aa, *aout = Ab;
    for (int s = 0; s < 47; s++) {
        mma_gemm<1, 0><<<dim3(8, 128), 256, SM1>>>(
            ain, nullptr, Gh, uin, Bb, uout, aout, nullptr, nullptr,
            DIM_L, DIM_L, DIM_L);
        float* tu = uin; uin = uout; uout = tu;
        __half* ta = ain; ain = aout; aout = ta;
    }
    // last step: write a split hi(aout) / lo(Ac)
    mma_gemm<1, 1><<<dim3(8, 128), 256, SM1>>>(
        ain, nullptr, Gh, uin, Bb, uout, aout, Ac, nullptr,
        DIM_L, DIM_L, DIM_L);

    // recon = a@W^T (fp16 2-product), N=784 guarded, B rows = padded W
    mma_gemm<2, 3><<<dim3(7, 128), 256, SM2>>>(
        aout, Ac, WR, nullptr, nullptr, nullptr, nullptr, nullptr, out,
        DIM_L, DIM_L, DIM_L);
}